// round 5
// baseline (speedup 1.0000x reference)
#include <cuda_runtime.h>
#include <cuda_bf16.h>
#include <cstdint>

// ---------------------------------------------------------------------------
// CNF_59133109731627 — split-bf16 mma.sync m16n8k16, round 5
//  main: R3 structure (both m-tiles live, grid 4096) + ldmatrix B-frags
//  hypernet: fused/k-split kernels (R4) with hyperB widened to 193 CTAs
// ---------------------------------------------------------------------------

#define D_      64
#define HID     512
#define WIDTH   64
#define BATCH   524288
#define BLOCK_P (WIDTH * D_)            // 4096
#define NP      (3 * BLOCK_P + WIDTH)   // 12352
#define SROW    144                     // padded smem row pitch (bytes)

// ---------------- device scratch ---------------------------------------------
__device__ float g_p2[HID];
__device__ float g_p3[NP];
__device__ __align__(16) __nv_bfloat16 g_whi[BLOCK_P];   // W  [w][d] hi
__device__ __align__(16) __nv_bfloat16 g_wlo[BLOCK_P];   // W  [w][d] lo
__device__ __align__(16) __nv_bfloat16 g_uthi[BLOCK_P];  // U^T[d][w] hi (gated)
__device__ __align__(16) __nv_bfloat16 g_utlo[BLOCK_P];  // U^T[d][w] lo
__device__ float g_B[WIDTH];
__device__ float g_wu[WIDTH];

// ---------------- helpers -----------------------------------------------------
__device__ __forceinline__ float fast_tanh(float x) {
    float e = __expf(2.0f * x);
    return 1.0f - __fdividef(2.0f, e + 1.0f);
}

__device__ __forceinline__ uint32_t smem_u32(const void* p) {
    uint32_t a;
    asm("{ .reg .u64 t; cvta.to.shared.u64 t, %1; cvt.u32.u64 %0, t; }"
        : "=r"(a) : "l"(p));
    return a;
}

__device__ __forceinline__ void mma_bf16(float d[4], const uint32_t a[4],
                                         const uint32_t b[2], const float c[4]) {
    asm volatile(
        "mma.sync.aligned.m16n8k16.row.col.f32.bf16.bf16.f32 "
        "{%0,%1,%2,%3}, {%4,%5,%6,%7}, {%8,%9}, {%10,%11,%12,%13};\n"
        : "=f"(d[0]), "=f"(d[1]), "=f"(d[2]), "=f"(d[3])
        : "r"(a[0]), "r"(a[1]), "r"(a[2]), "r"(a[3]),
          "r"(b[0]), "r"(b[1]),
          "f"(c[0]), "f"(c[1]), "f"(c[2]), "f"(c[3]));
}

__device__ __forceinline__ void ldsm_x4(uint32_t r[4], uint32_t saddr) {
    asm volatile(
        "ldmatrix.sync.aligned.m8n8.x4.shared.b16 {%0,%1,%2,%3}, [%4];"
        : "=r"(r[0]), "=r"(r[1]), "=r"(r[2]), "=r"(r[3]) : "r"(saddr));
}

__device__ __forceinline__ void split2(float2 v, uint32_t& hi, uint32_t& lo) {
    __nv_bfloat162 h = __float22bfloat162_rn(v);
    hi = *(uint32_t*)&h;
    float2 r;
    r.x = v.x - __bfloat162float(h.x);
    r.y = v.y - __bfloat162float(h.y);
    __nv_bfloat162 l = __float22bfloat162_rn(r);
    lo = *(uint32_t*)&l;
}

// ---------------- hyperA: p2 = tanh(tanh(t*W1+b1) @ W2 + b2) -------------------
__global__ void hyperA_kernel(const float* __restrict__ t,
                              const float* __restrict__ W1,
                              const float* __restrict__ b1,
                              const float* __restrict__ W2,
                              const float* __restrict__ b2) {
    __shared__ float p1[HID];
    __shared__ float red[8][32];
    const int tid = threadIdx.x;
    float tv = t[0];
    for (int k = tid; k < HID; k += 256)
        p1[k] = tanhf(tv * W1[k] + b1[k]);
    __syncthreads();
    const int x = tid & 31, y = tid >> 5;
    const int j = blockIdx.x * 32 + x;
    float acc = 0.0f;
#pragma unroll 8
    for (int i = 0; i < 64; i++) {
        int k = y + 8 * i;
        acc = fmaf(p1[k], W2[(size_t)k * HID + j], acc);
    }
    red[y][x] = acc;
    __syncthreads();
    if (tid < 32) {
        float s = b2[j];
#pragma unroll
        for (int yy = 0; yy < 8; yy++) s += red[yy][tid];
        g_p2[j] = tanhf(s);
    }
}

// ---------------- hyperB: p3 = p2 @ W3 + b3 ------------------------------------
// grid 193 x 512: 64 outputs per block, 8-way k-split (64-deep chains).
__global__ void hyperB_kernel(const float* __restrict__ W3,
                              const float* __restrict__ b3) {
    __shared__ float s2[HID];
    __shared__ float red[8][64];
    const int tid = threadIdx.x;
    if (tid < HID) s2[tid] = g_p2[tid];
    __syncthreads();
    const int x = tid & 63, y = tid >> 6;
    const int j = blockIdx.x * 64 + x;
    const bool ok = j < NP;
    float acc = 0.0f;
    if (ok) {
#pragma unroll 8
        for (int i = 0; i < 64; i++) {
            int k = y + 8 * i;
            acc = fmaf(s2[k], W3[(size_t)k * NP + j], acc);
        }
    }
    red[y][x] = acc;
    __syncthreads();
    if (y == 0 && ok) {
        float s = b3[j];
#pragma unroll
        for (int yy = 0; yy < 8; yy++) s += red[yy][x];
        g_p3[j] = s;
    }
}

// ---------------- hyper3: param prep ------------------------------------------
__global__ void hyper3_kernel() {
    __shared__ float prod[WIDTH];
    int w = blockIdx.x, d = threadIdx.x;
    int idx = w * D_ + d;
    float Wv = g_p3[idx];
    float gv = g_p3[2 * BLOCK_P + idx];
    float Uv = g_p3[BLOCK_P + idx] * (1.0f / (1.0f + __expf(-gv)));

    __nv_bfloat16 wh = __float2bfloat16_rn(Wv);
    g_whi[idx] = wh;
    g_wlo[idx] = __float2bfloat16_rn(Wv - __bfloat162float(wh));
    __nv_bfloat16 uh = __float2bfloat16_rn(Uv);
    g_uthi[d * WIDTH + w] = uh;
    g_utlo[d * WIDTH + w] = __float2bfloat16_rn(Uv - __bfloat162float(uh));

    prod[d] = Wv * Uv;
    __syncthreads();
    if (d == 0) {
        float s = 0.0f;
#pragma unroll
        for (int k = 0; k < D_; k++) s += prod[k];
        g_wu[w] = s;
    }
    if (w == 0) g_B[d] = g_p3[3 * BLOCK_P + d];
}

// ---------------- main batch kernel --------------------------------------------
// CTA = 128 threads = 4 warps; warp = 32 rows (two m16 tiles live in parallel).
__global__ __launch_bounds__(128)
void cnf_mma_kernel(const float* __restrict__ z, float* __restrict__ out) {
    __shared__ __align__(16) uint8_t sWhi[WIDTH * SROW];
    __shared__ __align__(16) uint8_t sWlo[WIDTH * SROW];
    __shared__ __align__(16) uint8_t sUthi[WIDTH * SROW];
    __shared__ __align__(16) uint8_t sUtlo[WIDTH * SROW];
    __shared__ float sB[WIDTH];
    __shared__ float swu[WIDTH];

    const int tid = threadIdx.x;

    // stage weights (128B global rows -> 144B pitch smem)
    {
        const uint4* s0 = (const uint4*)g_whi;
        const uint4* s1 = (const uint4*)g_wlo;
        const uint4* s2 = (const uint4*)g_uthi;
        const uint4* s3 = (const uint4*)g_utlo;
#pragma unroll
        for (int i = tid; i < 512; i += 128) {
            int r = i >> 3, c = i & 7;
            int dst = r * SROW + c * 16;
            *(uint4*)(sWhi + dst)  = s0[i];
            *(uint4*)(sWlo + dst)  = s1[i];
            *(uint4*)(sUthi + dst) = s2[i];
            *(uint4*)(sUtlo + dst) = s3[i];
        }
        if (tid < WIDTH) { sB[tid] = g_B[tid]; swu[tid] = g_wu[tid]; }
    }
    __syncthreads();

    const int lane = tid & 31;
    const int warp = tid >> 5;
    const int g = lane >> 2;     // group (row within 8)
    const int t = lane & 3;      // thread in group
    const int rrow = lane & 7;   // ldmatrix row provider
    const int qq = lane >> 3;    // ldmatrix matrix id

    const uint32_t baseWhi  = smem_u32(sWhi);
    const uint32_t baseWlo  = smem_u32(sWlo);
    const uint32_t baseUthi = smem_u32(sUthi);
    const uint32_t baseUtlo = smem_u32(sUtlo);
    const float inv = 1.0f / (float)WIDTH;

    const size_t rowbase = (size_t)blockIdx.x * 128 + (size_t)warp * 32;

    // ---- load z -> hi/lo A fragments (2 m-tiles x 4 k-tiles) ------------------
    uint32_t zh[2][4][4], zl[2][4][4];
#pragma unroll
    for (int m = 0; m < 2; m++) {
        const float2* zr0 = (const float2*)(z + (rowbase + 16 * m + g) * D_);
        const float2* zr1 = (const float2*)(z + (rowbase + 16 * m + g + 8) * D_);
        float2 v[4][4];
#pragma unroll
        for (int kt = 0; kt < 4; kt++) {
            v[kt][0] = zr0[8 * kt + t];
            v[kt][1] = zr1[8 * kt + t];
            v[kt][2] = zr0[8 * kt + 4 + t];
            v[kt][3] = zr1[8 * kt + 4 + t];
        }
#pragma unroll
        for (int kt = 0; kt < 4; kt++)
#pragma unroll
            for (int i = 0; i < 4; i++)
                split2(v[kt][i], zh[m][kt][i], zl[m][kt][i]);
    }

    // ---- GEMM1: S = zh*Wh + zl*Wh + zh*Wl --------------------------------------
    float S[2][8][4];
#pragma unroll
    for (int m = 0; m < 2; m++)
#pragma unroll
        for (int n = 0; n < 8; n++)
#pragma unroll
            for (int i = 0; i < 4; i++) S[m][n][i] = 0.0f;

#pragma unroll
    for (int n = 0; n < 8; n++) {
        const uint32_t off = (uint32_t)((8 * n + rrow) * SROW + qq * 16);
        uint32_t bh[8], bl[8];
        ldsm_x4(&bh[0], baseWhi + off);
        ldsm_x4(&bh[4], baseWhi + off + 64);
        ldsm_x4(&bl[0], baseWlo + off);
        ldsm_x4(&bl[4], baseWlo + off + 64);
#pragma unroll
        for (int kt = 0; kt < 4; kt++) {
            mma_bf16(S[0][n], zh[0][kt], &bh[2 * kt], S[0][n]);
            mma_bf16(S[1][n], zh[1][kt], &bh[2 * kt], S[1][n]);
            mma_bf16(S[0][n], zl[0][kt], &bh[2 * kt], S[0][n]);
            mma_bf16(S[1][n], zl[1][kt], &bh[2 * kt], S[1][n]);
            mma_bf16(S[0][n], zh[0][kt], &bl[2 * kt], S[0][n]);
            mma_bf16(S[1][n], zh[1][kt], &bl[2 * kt], S[1][n]);
        }
    }

    // ---- epilogue: h = tanh(S+B), trace, repack into GEMM2 A frags -------------
    uint32_t hh[2][4][4], hl[2][4][4];
    float tr[2][2] = {{0.0f, 0.0f}, {0.0f, 0.0f}};
#pragma unroll
    for (int m = 0; m < 2; m++) {
#pragma unroll
        for (int n = 0; n < 8; n++) {
            float2 bb = *(const float2*)&sB[8 * n + 2 * t];
            float2 ww = *(const float2*)&swu[8 * n + 2 * t];
            float h0 = fast_tanh(S[m][n][0] + bb.x);
            float h1 = fast_tanh(S[m][n][1] + bb.y);
            float h2 = fast_tanh(S[m][n][2] + bb.x);
            float h3 = fast_tanh(S[m][n][3] + bb.y);
            tr[m][0] = fmaf(1.0f - h0 * h0, ww.x, tr[m][0]);
            tr[m][0] = fmaf(1.0f - h1 * h1, ww.y, tr[m][0]);
            tr[m][1] = fmaf(1.0f - h2 * h2, ww.x, tr[m][1]);
            tr[m][1] = fmaf(1.0f - h3 * h3, ww.y, tr[m][1]);
            int kt = n >> 1;
            int o = (n & 1) ? 2 : 0;
            split2(make_float2(h0, h1), hh[m][kt][o],     hl[m][kt][o]);
            split2(make_float2(h2, h3), hh[m][kt][o + 1], hl[m][kt][o + 1]);
        }
    }

    // ---- GEMM2: DZ = hh*Uth + hl*Uth + hh*Utl ----------------------------------
    float DZ[2][8][4];
#pragma unroll
    for (int m = 0; m < 2; m++)
#pragma unroll
        for (int n = 0; n < 8; n++)
#pragma unroll
            for (int i = 0; i < 4; i++) DZ[m][n][i] = 0.0f;

#pragma unroll
    for (int n = 0; n < 8; n++) {
        const uint32_t off = (uint32_t)((8 * n + rrow) * SROW + qq * 16);
        uint32_t bh[8], bl[8];
        ldsm_x4(&bh[0], baseUthi + off);
        ldsm_x4(&bh[4], baseUthi + off + 64);
        ldsm_x4(&bl[0], baseUtlo + off);
        ldsm_x4(&bl[4], baseUtlo + off + 64);
#pragma unroll
        for (int kt = 0; kt < 4; kt++) {
            mma_bf16(DZ[0][n], hh[0][kt], &bh[2 * kt], DZ[0][n]);
            mma_bf16(DZ[1][n], hh[1][kt], &bh[2 * kt], DZ[1][n]);
            mma_bf16(DZ[0][n], hl[0][kt], &bh[2 * kt], DZ[0][n]);
            mma_bf16(DZ[1][n], hl[1][kt], &bh[2 * kt], DZ[1][n]);
            mma_bf16(DZ[0][n], hh[0][kt], &bl[2 * kt], DZ[0][n]);
            mma_bf16(DZ[1][n], hh[1][kt], &bl[2 * kt], DZ[1][n]);
        }
    }

    // ---- store dz/64 ------------------------------------------------------------
#pragma unroll
    for (int m = 0; m < 2; m++) {
        size_t r0 = rowbase + 16 * m + g;
#pragma unroll
        for (int n = 0; n < 8; n++) {
            int col = 8 * n + 2 * t;
            *(float2*)(out + r0 * D_ + col) =
                make_float2(DZ[m][n][0] * inv, DZ[m][n][1] * inv);
            *(float2*)(out + (r0 + 8) * D_ + col) =
                make_float2(DZ[m][n][2] * inv, DZ[m][n][3] * inv);
        }
    }

    // ---- trace: reduce over t, write -tr/64 --------------------------------------
#pragma unroll
    for (int m = 0; m < 2; m++)
#pragma unroll
        for (int rh = 0; rh < 2; rh++) {
            float v = tr[m][rh];
            v += __shfl_xor_sync(0xFFFFFFFFu, v, 1);
            v += __shfl_xor_sync(0xFFFFFFFFu, v, 2);
            tr[m][rh] = v;
        }
    {
        float trv = (t == 0) ? tr[0][0] : (t == 1) ? tr[0][1]
                  : (t == 2) ? tr[1][0] : tr[1][1];
        size_t row = rowbase + (size_t)g + 8 * (t & 1) + 16 * (t >> 1);
        out[(size_t)BATCH * D_ + row] = -trv * inv;
    }
}

// ---------------------------------------------------------------------------
extern "C" void kernel_launch(void* const* d_in, const int* in_sizes, int n_in,
                              void* d_out, int out_size) {
    const float* t  = (const float*)d_in[0];
    const float* z  = (const float*)d_in[1];
    const float* W1 = (const float*)d_in[3];
    const float* b1 = (const float*)d_in[4];
    const float* W2 = (const float*)d_in[5];
    const float* b2 = (const float*)d_in[6];
    const float* W3 = (const float*)d_in[7];
    const float* b3 = (const float*)d_in[8];
    float* out = (float*)d_out;

    hyperA_kernel<<<16, 256>>>(t, W1, b1, W2, b2);
    hyperB_kernel<<<(NP + 63) / 64, 512>>>(W3, b3);
    hyper3_kernel<<<WIDTH, D_>>>();
    cnf_mma_kernel<<<BATCH / 128, 128>>>(z, out);
}

// round 6
// speedup vs baseline: 1.4092x; 1.4092x over previous
#include <cuda_runtime.h>
#include <cuda_fp16.h>
#include <cstdint>

// ---------------------------------------------------------------------------
// CNF_59133109731627 — round 6: fp16 2-pass split GEMMs (mma.sync m16n8k16 f16)
//  S  = (zh + zl) @ Wh^T        zh+zl: exact 2-term fp16 split of z
//  h  = tanh(S+B);  tr = sum (1-h^2) wu
//  dz = (hh + hl) @ Uth / 64    hh+hl: exact 2-term fp16 split of h
//  W, Ut single-rounded to fp16 (rel err ~2^-12)
//  warp = 16 rows (one m16 tile), CTA = 4 warps = 64 rows, grid 8192
// ---------------------------------------------------------------------------

#define D_      64
#define HID     512
#define WIDTH   64
#define BATCH   524288
#define BLOCK_P (WIDTH * D_)            // 4096
#define NP      (3 * BLOCK_P + WIDTH)   // 12352
#define SROW    144                     // padded smem row pitch (bytes)

// ---------------- device scratch ---------------------------------------------
__device__ float g_p2[HID];
__device__ float g_p3[NP];
__device__ __align__(16) __half g_wh16[BLOCK_P];    // W  [w][d] fp16
__device__ __align__(16) __half g_uth16[BLOCK_P];   // U^T[d][w] fp16 (gated)
__device__ float g_B[WIDTH];
__device__ float g_wu[WIDTH];

// ---------------- helpers -----------------------------------------------------
__device__ __forceinline__ float fast_tanh(float x) {
    float e = __expf(2.0f * x);
    return 1.0f - __fdividef(2.0f, e + 1.0f);
}

__device__ __forceinline__ uint32_t smem_u32(const void* p) {
    uint32_t a;
    asm("{ .reg .u64 t; cvta.to.shared.u64 t, %1; cvt.u32.u64 %0, t; }"
        : "=r"(a) : "l"(p));
    return a;
}

__device__ __forceinline__ void mma_f16(float d[4], const uint32_t a[4],
                                        const uint32_t b[2], const float c[4]) {
    asm volatile(
        "mma.sync.aligned.m16n8k16.row.col.f32.f16.f16.f32 "
        "{%0,%1,%2,%3}, {%4,%5,%6,%7}, {%8,%9}, {%10,%11,%12,%13};\n"
        : "=f"(d[0]), "=f"(d[1]), "=f"(d[2]), "=f"(d[3])
        : "r"(a[0]), "r"(a[1]), "r"(a[2]), "r"(a[3]),
          "r"(b[0]), "r"(b[1]),
          "f"(c[0]), "f"(c[1]), "f"(c[2]), "f"(c[3]));
}

__device__ __forceinline__ void ldsm_x4(uint32_t r[4], uint32_t saddr) {
    asm volatile(
        "ldmatrix.sync.aligned.m8n8.x4.shared.b16 {%0,%1,%2,%3}, [%4];"
        : "=r"(r[0]), "=r"(r[1]), "=r"(r[2]), "=r"(r[3]) : "r"(saddr));
}

// exact 2-term fp16 split of a float2
__device__ __forceinline__ void split2h(float2 v, uint32_t& hi, uint32_t& lo) {
    __half2 h = __float22half2_rn(v);
    hi = *(uint32_t*)&h;
    float2 r;
    r.x = v.x - __half2float(__low2half(h));
    r.y = v.y - __half2float(__high2half(h));
    __half2 l = __float22half2_rn(r);
    lo = *(uint32_t*)&l;
}

// ---------------- hyperA: p2 = tanh(tanh(t*W1+b1) @ W2 + b2) -------------------
__global__ void hyperA_kernel(const float* __restrict__ t,
                              const float* __restrict__ W1,
                              const float* __restrict__ b1,
                              const float* __restrict__ W2,
                              const float* __restrict__ b2) {
    __shared__ float p1[HID];
    __shared__ float red[8][32];
    const int tid = threadIdx.x;
    float tv = t[0];
    for (int k = tid; k < HID; k += 256)
        p1[k] = tanhf(tv * W1[k] + b1[k]);
    __syncthreads();
    const int x = tid & 31, y = tid >> 5;
    const int j = blockIdx.x * 32 + x;
    float acc = 0.0f;
#pragma unroll 8
    for (int i = 0; i < 64; i++) {
        int k = y + 8 * i;
        acc = fmaf(p1[k], W2[(size_t)k * HID + j], acc);
    }
    red[y][x] = acc;
    __syncthreads();
    if (tid < 32) {
        float s = b2[j];
#pragma unroll
        for (int yy = 0; yy < 8; yy++) s += red[yy][tid];
        g_p2[j] = tanhf(s);
    }
}

// ---------------- hyperB: p3 = p2 @ W3 + b3 ------------------------------------
__global__ void hyperB_kernel(const float* __restrict__ W3,
                              const float* __restrict__ b3) {
    __shared__ float s2[HID];
    __shared__ float red[8][64];
    const int tid = threadIdx.x;
    if (tid < HID) s2[tid] = g_p2[tid];
    __syncthreads();
    const int x = tid & 63, y = tid >> 6;
    const int j = blockIdx.x * 64 + x;
    const bool ok = j < NP;
    float acc = 0.0f;
    if (ok) {
#pragma unroll 8
        for (int i = 0; i < 64; i++) {
            int k = y + 8 * i;
            acc = fmaf(s2[k], W3[(size_t)k * NP + j], acc);
        }
    }
    red[y][x] = acc;
    __syncthreads();
    if (y == 0 && ok) {
        float s = b3[j];
#pragma unroll
        for (int yy = 0; yy < 8; yy++) s += red[yy][x];
        g_p3[j] = s;
    }
}

// ---------------- hyper3: param prep (fp16 W, gated U^T) ------------------------
__global__ void hyper3_kernel() {
    __shared__ float prod[WIDTH];
    int w = blockIdx.x, d = threadIdx.x;
    int idx = w * D_ + d;
    float Wv = g_p3[idx];
    float gv = g_p3[2 * BLOCK_P + idx];
    float Uv = g_p3[BLOCK_P + idx] * (1.0f / (1.0f + __expf(-gv)));

    g_wh16[idx] = __float2half_rn(Wv);
    g_uth16[d * WIDTH + w] = __float2half_rn(Uv);

    prod[d] = Wv * Uv;
    __syncthreads();
    if (d == 0) {
        float s = 0.0f;
#pragma unroll
        for (int k = 0; k < D_; k++) s += prod[k];
        g_wu[w] = s;
    }
    if (w == 0) g_B[d] = g_p3[3 * BLOCK_P + d];
}

// ---------------- main batch kernel --------------------------------------------
// CTA = 128 threads = 4 warps; warp = 16 rows (one m16 tile); grid = 8192.
__global__ __launch_bounds__(128)
void cnf_mma_kernel(const float* __restrict__ z, float* __restrict__ out) {
    __shared__ __align__(16) uint8_t sWh[WIDTH * SROW];
    __shared__ __align__(16) uint8_t sUth[WIDTH * SROW];
    __shared__ float sB[WIDTH];
    __shared__ float swu[WIDTH];

    const int tid = threadIdx.x;

    // stage weights (128B global rows -> 144B pitch smem)
    {
        const uint4* s0 = (const uint4*)g_wh16;
        const uint4* s1 = (const uint4*)g_uth16;
#pragma unroll
        for (int i = tid; i < 512; i += 128) {
            int r = i >> 3, c = i & 7;
            int dst = r * SROW + c * 16;
            *(uint4*)(sWh + dst)  = s0[i];
            *(uint4*)(sUth + dst) = s1[i];
        }
        if (tid < WIDTH) { sB[tid] = g_B[tid]; swu[tid] = g_wu[tid]; }
    }
    __syncthreads();

    const int lane = tid & 31;
    const int warp = tid >> 5;
    const int g = lane >> 2;     // group (row within 8)
    const int t = lane & 3;      // thread in group
    const int rrow = lane & 7;   // ldmatrix row provider
    const int qq = lane >> 3;    // ldmatrix matrix id

    const uint32_t baseWh  = smem_u32(sWh);
    const uint32_t baseUth = smem_u32(sUth);
    const float inv = 1.0f / (float)WIDTH;

    const size_t r0 = (size_t)blockIdx.x * 64 + (size_t)warp * 16 + g;

    // ---- load z rows r0, r0+8 -> exact fp16 2-term A fragments ---------------
    uint32_t zh[4][4], zl[4][4];
    {
        const float2* zr0 = (const float2*)(z + r0 * D_);
        const float2* zr1 = (const float2*)(z + (r0 + 8) * D_);
        float2 v[4][4];
#pragma unroll
        for (int kt = 0; kt < 4; kt++) {
            v[kt][0] = zr0[8 * kt + t];
            v[kt][1] = zr1[8 * kt + t];
            v[kt][2] = zr0[8 * kt + 4 + t];
            v[kt][3] = zr1[8 * kt + 4 + t];
        }
#pragma unroll
        for (int kt = 0; kt < 4; kt++)
#pragma unroll
            for (int i = 0; i < 4; i++)
                split2h(v[kt][i], zh[kt][i], zl[kt][i]);
    }

    // ---- GEMM1: S = (zh + zl) * Wh -------------------------------------------
    float S[8][4];
#pragma unroll
    for (int n = 0; n < 8; n++) {
        const uint32_t off = (uint32_t)((8 * n + rrow) * SROW + qq * 16);
        uint32_t bh[8];
        ldsm_x4(&bh[0], baseWh + off);
        ldsm_x4(&bh[4], baseWh + off + 64);
#pragma unroll
        for (int i = 0; i < 4; i++) S[n][i] = 0.0f;
#pragma unroll
        for (int kt = 0; kt < 4; kt++) {
            mma_f16(S[n], zh[kt], &bh[2 * kt], S[n]);
            mma_f16(S[n], zl[kt], &bh[2 * kt], S[n]);
        }
    }

    // ---- epilogue: h = tanh(S+B), trace, exact fp16 split into A2 frags -------
    uint32_t hh[4][4], hl[4][4];
    float tr0 = 0.0f, tr1 = 0.0f;
#pragma unroll
    for (int n = 0; n < 8; n++) {
        float2 bb = *(const float2*)&sB[8 * n + 2 * t];
        float2 ww = *(const float2*)&swu[8 * n + 2 * t];
        float h0 = fast_tanh(S[n][0] + bb.x);
        float h1 = fast_tanh(S[n][1] + bb.y);
        float h2 = fast_tanh(S[n][2] + bb.x);
        float h3 = fast_tanh(S[n][3] + bb.y);
        tr0 = fmaf(1.0f - h0 * h0, ww.x, tr0);
        tr0 = fmaf(1.0f - h1 * h1, ww.y, tr0);
        tr1 = fmaf(1.0f - h2 * h2, ww.x, tr1);
        tr1 = fmaf(1.0f - h3 * h3, ww.y, tr1);
        int kt = n >> 1;
        int o = (n & 1) ? 2 : 0;
        split2h(make_float2(h0, h1), hh[kt][o],     hl[kt][o]);
        split2h(make_float2(h2, h3), hh[kt][o + 1], hl[kt][o + 1]);
    }

    // ---- GEMM2: DZ = (hh + hl) * Uth ------------------------------------------
    float DZ[8][4];
#pragma unroll
    for (int n = 0; n < 8; n++) {
        const uint32_t off = (uint32_t)((8 * n + rrow) * SROW + qq * 16);
        uint32_t bh[8];
        ldsm_x4(&bh[0], baseUth + off);
        ldsm_x4(&bh[4], baseUth + off + 64);
#pragma unroll
        for (int i = 0; i < 4; i++) DZ[n][i] = 0.0f;
#pragma unroll
        for (int kt = 0; kt < 4; kt++) {
            mma_f16(DZ[n], hh[kt], &bh[2 * kt], DZ[n]);
            mma_f16(DZ[n], hl[kt], &bh[2 * kt], DZ[n]);
        }
    }

    // ---- store dz/64 ------------------------------------------------------------
#pragma unroll
    for (int n = 0; n < 8; n++) {
        int col = 8 * n + 2 * t;
        *(float2*)(out + r0 * D_ + col) =
            make_float2(DZ[n][0] * inv, DZ[n][1] * inv);
        *(float2*)(out + (r0 + 8) * D_ + col) =
            make_float2(DZ[n][2] * inv, DZ[n][3] * inv);
    }

    // ---- trace: reduce over quad, write -tr/64 -----------------------------------
    tr0 += __shfl_xor_sync(0xFFFFFFFFu, tr0, 1);
    tr0 += __shfl_xor_sync(0xFFFFFFFFu, tr0, 2);
    tr1 += __shfl_xor_sync(0xFFFFFFFFu, tr1, 1);
    tr1 += __shfl_xor_sync(0xFFFFFFFFu, tr1, 2);
    if (t == 0) out[(size_t)BATCH * D_ + r0] = -tr0 * inv;
    if (t == 1) out[(size_t)BATCH * D_ + r0 + 8] = -tr1 * inv;
}

// ---------------------------------------------------------------------------
extern "C" void kernel_launch(void* const* d_in, const int* in_sizes, int n_in,
                              void* d_out, int out_size) {
    const float* t  = (const float*)d_in[0];
    const float* z  = (const float*)d_in[1];
    const float* W1 = (const float*)d_in[3];
    const float* b1 = (const float*)d_in[4];
    const float* W2 = (const float*)d_in[5];
    const float* b2 = (const float*)d_in[6];
    const float* W3 = (const float*)d_in[7];
    const float* b3 = (const float*)d_in[8];
    float* out = (float*)d_out;

    hyperA_kernel<<<16, 256>>>(t, W1, b1, W2, b2);
    hyperB_kernel<<<(NP + 63) / 64, 512>>>(W3, b3);
    hyper3_kernel<<<WIDTH, D_>>>();
    cnf_mma_kernel<<<BATCH / 64, 128>>>(z, out);
}

// round 7
// speedup vs baseline: 1.5163x; 1.0760x over previous
#include <cuda_runtime.h>
#include <cuda_fp16.h>
#include <cstdint>

// ---------------------------------------------------------------------------
// CNF_59133109731627 — round 7: fp16 2-pass split GEMMs + d-permutation so
// z loads and dz stores are float4 (halves LSU wavefronts vs round 6).
//  Permutation within each 16-group of d: frag pos f=8b+2t+i <-> col 4t+2b+i.
//  W columns (GEMM1 k-dim) and Ut rows (GEMM2 n-dim) stored pre-permuted.
// ---------------------------------------------------------------------------

#define D_      64
#define HID     512
#define WIDTH   64
#define BATCH   524288
#define BLOCK_P (WIDTH * D_)            // 4096
#define NP      (3 * BLOCK_P + WIDTH)   // 12352
#define SROW    144                     // padded smem row pitch (bytes)

// ---------------- device scratch ---------------------------------------------
__device__ float g_p2[HID];
__device__ float g_p3[NP];
__device__ __align__(16) __half g_wh16[BLOCK_P];    // W  [w][dp] fp16 (d-cols permuted)
__device__ __align__(16) __half g_uth16[BLOCK_P];   // U^T[dp][w] fp16 (d-rows permuted)
__device__ float g_B[WIDTH];
__device__ float g_wu[WIDTH];

// ---------------- helpers -----------------------------------------------------
__device__ __forceinline__ float fast_tanh(float x) {
    float e = __expf(2.0f * x);
    return 1.0f - __fdividef(2.0f, e + 1.0f);
}

__device__ __forceinline__ uint32_t smem_u32(const void* p) {
    uint32_t a;
    asm("{ .reg .u64 t; cvta.to.shared.u64 t, %1; cvt.u32.u64 %0, t; }"
        : "=r"(a) : "l"(p));
    return a;
}

__device__ __forceinline__ void mma_f16(float d[4], const uint32_t a[4],
                                        const uint32_t b[2], const float c[4]) {
    asm volatile(
        "mma.sync.aligned.m16n8k16.row.col.f32.f16.f16.f32 "
        "{%0,%1,%2,%3}, {%4,%5,%6,%7}, {%8,%9}, {%10,%11,%12,%13};\n"
        : "=f"(d[0]), "=f"(d[1]), "=f"(d[2]), "=f"(d[3])
        : "r"(a[0]), "r"(a[1]), "r"(a[2]), "r"(a[3]),
          "r"(b[0]), "r"(b[1]),
          "f"(c[0]), "f"(c[1]), "f"(c[2]), "f"(c[3]));
}

__device__ __forceinline__ void ldsm_x4(uint32_t r[4], uint32_t saddr) {
    asm volatile(
        "ldmatrix.sync.aligned.m8n8.x4.shared.b16 {%0,%1,%2,%3}, [%4];"
        : "=r"(r[0]), "=r"(r[1]), "=r"(r[2]), "=r"(r[3]) : "r"(saddr));
}

// exact 2-term fp16 split of a float2
__device__ __forceinline__ void split2h(float2 v, uint32_t& hi, uint32_t& lo) {
    __half2 h = __float22half2_rn(v);
    hi = *(uint32_t*)&h;
    float2 r;
    r.x = v.x - __half2float(__low2half(h));
    r.y = v.y - __half2float(__high2half(h));
    __half2 l = __float22half2_rn(r);
    lo = *(uint32_t*)&l;
}

// ---------------- hyperA: p2 = tanh(tanh(t*W1+b1) @ W2 + b2) -------------------
__global__ void hyperA_kernel(const float* __restrict__ t,
                              const float* __restrict__ W1,
                              const float* __restrict__ b1,
                              const float* __restrict__ W2,
                              const float* __restrict__ b2) {
    __shared__ float p1[HID];
    __shared__ float red[8][32];
    const int tid = threadIdx.x;
    float tv = t[0];
    for (int k = tid; k < HID; k += 256)
        p1[k] = tanhf(tv * W1[k] + b1[k]);
    __syncthreads();
    const int x = tid & 31, y = tid >> 5;
    const int j = blockIdx.x * 32 + x;
    float acc = 0.0f;
#pragma unroll 8
    for (int i = 0; i < 64; i++) {
        int k = y + 8 * i;
        acc = fmaf(p1[k], W2[(size_t)k * HID + j], acc);
    }
    red[y][x] = acc;
    __syncthreads();
    if (tid < 32) {
        float s = b2[j];
#pragma unroll
        for (int yy = 0; yy < 8; yy++) s += red[yy][tid];
        g_p2[j] = tanhf(s);
    }
}

// ---------------- hyperB: p3 = p2 @ W3 + b3 ------------------------------------
__global__ void hyperB_kernel(const float* __restrict__ W3,
                              const float* __restrict__ b3) {
    __shared__ float s2[HID];
    __shared__ float red[8][64];
    const int tid = threadIdx.x;
    if (tid < HID) s2[tid] = g_p2[tid];
    __syncthreads();
    const int x = tid & 63, y = tid >> 6;
    const int j = blockIdx.x * 64 + x;
    const bool ok = j < NP;
    float acc = 0.0f;
    if (ok) {
#pragma unroll 8
        for (int i = 0; i < 64; i++) {
            int k = y + 8 * i;
            acc = fmaf(s2[k], W3[(size_t)k * NP + j], acc);
        }
    }
    red[y][x] = acc;
    __syncthreads();
    if (y == 0 && ok) {
        float s = b3[j];
#pragma unroll
        for (int yy = 0; yy < 8; yy++) s += red[yy][x];
        g_p3[j] = s;
    }
}

// ---------------- hyper3: param prep (fp16, d-permuted) -------------------------
// frag position f = 8b + 2t + i  <->  original col dd = 4t + 2b + i  (within 16)
__global__ void hyper3_kernel() {
    __shared__ float prod[WIDTH];
    int w = blockIdx.x, d = threadIdx.x;
    int idx = w * D_ + d;
    float Wv = g_p3[idx];
    float gv = g_p3[2 * BLOCK_P + idx];
    float Uv = g_p3[BLOCK_P + idx] * (1.0f / (1.0f + __expf(-gv)));

    // inverse permutation: original col d -> fragment position dp
    int dd = d & 15;
    int f = ((dd >> 1) & 1) * 8 + (dd >> 2) * 2 + (dd & 1);
    int dp = (d & ~15) | f;

    g_wh16[w * D_ + dp] = __float2half_rn(Wv);      // permute W's d-columns
    g_uth16[dp * WIDTH + w] = __float2half_rn(Uv);  // permute Ut's d-rows

    prod[d] = Wv * Uv;
    __syncthreads();
    if (d == 0) {
        float s = 0.0f;
#pragma unroll
        for (int k = 0; k < D_; k++) s += prod[k];
        g_wu[w] = s;
    }
    if (w == 0) g_B[d] = g_p3[3 * BLOCK_P + d];
}

// ---------------- main batch kernel --------------------------------------------
// CTA = 128 threads = 4 warps; warp = 16 rows (one m16 tile); grid = 8192.
__global__ __launch_bounds__(128)
void cnf_mma_kernel(const float* __restrict__ z, float* __restrict__ out) {
    __shared__ __align__(16) uint8_t sWh[WIDTH * SROW];
    __shared__ __align__(16) uint8_t sUth[WIDTH * SROW];
    __shared__ float sB[WIDTH];
    __shared__ float swu[WIDTH];

    const int tid = threadIdx.x;

    // stage weights (128B global rows -> 144B pitch smem)
    {
        const uint4* s0 = (const uint4*)g_wh16;
        const uint4* s1 = (const uint4*)g_uth16;
#pragma unroll
        for (int i = tid; i < 512; i += 128) {
            int r = i >> 3, c = i & 7;
            int dst = r * SROW + c * 16;
            *(uint4*)(sWh + dst)  = s0[i];
            *(uint4*)(sUth + dst) = s1[i];
        }
        if (tid < WIDTH) { sB[tid] = g_B[tid]; swu[tid] = g_wu[tid]; }
    }
    __syncthreads();

    const int lane = tid & 31;
    const int warp = tid >> 5;
    const int g = lane >> 2;     // group (row within 8)
    const int t = lane & 3;      // thread in group
    const int rrow = lane & 7;   // ldmatrix row provider
    const int qq = lane >> 3;    // ldmatrix matrix id

    const uint32_t baseWh  = smem_u32(sWh);
    const uint32_t baseUth = smem_u32(sUth);
    const float inv = 1.0f / (float)WIDTH;

    const size_t r0 = (size_t)blockIdx.x * 64 + (size_t)warp * 16 + g;

    // ---- load z rows r0, r0+8 as float4 -> exact fp16 2-term A frags ----------
    // thread t reads orig cols 16kt+4t..4t+3; frag pos: x,y -> (2t,2t+1), z,w -> (8+2t,8+2t+1)
    uint32_t zh[4][4], zl[4][4];
    {
        const float4* zr0 = (const float4*)(z + r0 * D_);
        const float4* zr1 = (const float4*)(z + (r0 + 8) * D_);
#pragma unroll
        for (int kt = 0; kt < 4; kt++) {
            float4 v0 = zr0[4 * kt + t];
            float4 v1 = zr1[4 * kt + t];
            split2h(make_float2(v0.x, v0.y), zh[kt][0], zl[kt][0]);
            split2h(make_float2(v1.x, v1.y), zh[kt][1], zl[kt][1]);
            split2h(make_float2(v0.z, v0.w), zh[kt][2], zl[kt][2]);
            split2h(make_float2(v1.z, v1.w), zh[kt][3], zl[kt][3]);
        }
    }

    // ---- GEMM1: S = (zh + zl) * Wh (k-dim permuted consistently) ---------------
    float S[8][4];
#pragma unroll
    for (int n = 0; n < 8; n++) {
        const uint32_t off = (uint32_t)((8 * n + rrow) * SROW + qq * 16);
        uint32_t bh[8];
        ldsm_x4(&bh[0], baseWh + off);
        ldsm_x4(&bh[4], baseWh + off + 64);
#pragma unroll
        for (int i = 0; i < 4; i++) S[n][i] = 0.0f;
#pragma unroll
        for (int kt = 0; kt < 4; kt++) {
            mma_f16(S[n], zh[kt], &bh[2 * kt], S[n]);
            mma_f16(S[n], zl[kt], &bh[2 * kt], S[n]);
        }
    }

    // ---- epilogue: h = tanh(S+B), trace, exact fp16 split into A2 frags --------
    uint32_t hh[4][4], hl[4][4];
    float tr0 = 0.0f, tr1 = 0.0f;
#pragma unroll
    for (int n = 0; n < 8; n++) {
        float2 bb = *(const float2*)&sB[8 * n + 2 * t];
        float2 ww = *(const float2*)&swu[8 * n + 2 * t];
        float h0 = fast_tanh(S[n][0] + bb.x);
        float h1 = fast_tanh(S[n][1] + bb.y);
        float h2 = fast_tanh(S[n][2] + bb.x);
        float h3 = fast_tanh(S[n][3] + bb.y);
        tr0 = fmaf(1.0f - h0 * h0, ww.x, tr0);
        tr0 = fmaf(1.0f - h1 * h1, ww.y, tr0);
        tr1 = fmaf(1.0f - h2 * h2, ww.x, tr1);
        tr1 = fmaf(1.0f - h3 * h3, ww.y, tr1);
        int kt = n >> 1;
        int o = (n & 1) ? 2 : 0;
        split2h(make_float2(h0, h1), hh[kt][o],     hl[kt][o]);
        split2h(make_float2(h2, h3), hh[kt][o + 1], hl[kt][o + 1]);
    }

    // ---- GEMM2: DZ = (hh + hl) * Uth (n-dim = d, rows pre-permuted) -------------
    float DZ[8][4];
#pragma unroll
    for (int n = 0; n < 8; n++) {
        const uint32_t off = (uint32_t)((8 * n + rrow) * SROW + qq * 16);
        uint32_t bh[8];
        ldsm_x4(&bh[0], baseUth + off);
        ldsm_x4(&bh[4], baseUth + off + 64);
#pragma unroll
        for (int i = 0; i < 4; i++) DZ[n][i] = 0.0f;
#pragma unroll
        for (int kt = 0; kt < 4; kt++) {
            mma_f16(DZ[n], hh[kt], &bh[2 * kt], DZ[n]);
            mma_f16(DZ[n], hl[kt], &bh[2 * kt], DZ[n]);
        }
    }

    // ---- store dz/64 as float4 ----------------------------------------------------
    // n-tile pair (2j, 2j+1): thread t owns actual cols 16j+4t..4t+3
#pragma unroll
    for (int j = 0; j < 4; j++) {
        int col = 16 * j + 4 * t;
        *(float4*)(out + r0 * D_ + col) =
            make_float4(DZ[2 * j][0] * inv, DZ[2 * j][1] * inv,
                        DZ[2 * j + 1][0] * inv, DZ[2 * j + 1][1] * inv);
        *(float4*)(out + (r0 + 8) * D_ + col) =
            make_float4(DZ[2 * j][2] * inv, DZ[2 * j][3] * inv,
                        DZ[2 * j + 1][2] * inv, DZ[2 * j + 1][3] * inv);
    }

    // ---- trace: reduce over quad, write -tr/64 -------------------------------------
    tr0 += __shfl_xor_sync(0xFFFFFFFFu, tr0, 1);
    tr0 += __shfl_xor_sync(0xFFFFFFFFu, tr0, 2);
    tr1 += __shfl_xor_sync(0xFFFFFFFFu, tr1, 1);
    tr1 += __shfl_xor_sync(0xFFFFFFFFu, tr1, 2);
    if (t == 0) out[(size_t)BATCH * D_ + r0] = -tr0 * inv;
    if (t == 1) out[(size_t)BATCH * D_ + r0 + 8] = -tr1 * inv;
}

// ---------------------------------------------------------------------------
extern "C" void kernel_launch(void* const* d_in, const int* in_sizes, int n_in,
                              void* d_out, int out_size) {
    const float* t  = (const float*)d_in[0];
    const float* z  = (const float*)d_in[1];
    const float* W1 = (const float*)d_in[3];
    const float* b1 = (const float*)d_in[4];
    const float* W2 = (const float*)d_in[5];
    const float* b2 = (const float*)d_in[6];
    const float* W3 = (const float*)d_in[7];
    const float* b3 = (const float*)d_in[8];
    float* out = (float*)d_out;

    hyperA_kernel<<<16, 256>>>(t, W1, b1, W2, b2);
    hyperB_kernel<<<(NP + 63) / 64, 512>>>(W3, b3);
    hyper3_kernel<<<WIDTH, D_>>>();
    cnf_mma_kernel<<<BATCH / 64, 128>>>(z, out);
}

// round 8
// speedup vs baseline: 1.5542x; 1.0250x over previous
#include <cuda_runtime.h>
#include <cuda_fp16.h>
#include <cstdint>

// ---------------------------------------------------------------------------
// CNF_59133109731627 — round 8: R7 + occupancy bound on main kernel +
// wider/shallower hypernet kernels.
// ---------------------------------------------------------------------------

#define D_      64
#define HID     512
#define WIDTH   64
#define BATCH   524288
#define BLOCK_P (WIDTH * D_)            // 4096
#define NP      (3 * BLOCK_P + WIDTH)   // 12352
#define SROW    144                     // padded smem row pitch (bytes)

// ---------------- device scratch ---------------------------------------------
__device__ float g_p2[HID];
__device__ float g_p3[NP];
__device__ __align__(16) __half g_wh16[BLOCK_P];    // W  [w][dp] fp16 (d-cols permuted)
__device__ __align__(16) __half g_uth16[BLOCK_P];   // U^T[dp][w] fp16 (d-rows permuted)
__device__ float g_B[WIDTH];
__device__ float g_wu[WIDTH];

// ---------------- helpers -----------------------------------------------------
__device__ __forceinline__ float fast_tanh(float x) {
    float e = __expf(2.0f * x);
    return 1.0f - __fdividef(2.0f, e + 1.0f);
}

__device__ __forceinline__ uint32_t smem_u32(const void* p) {
    uint32_t a;
    asm("{ .reg .u64 t; cvta.to.shared.u64 t, %1; cvt.u32.u64 %0, t; }"
        : "=r"(a) : "l"(p));
    return a;
}

__device__ __forceinline__ void mma_f16(float d[4], const uint32_t a[4],
                                        const uint32_t b[2], const float c[4]) {
    asm volatile(
        "mma.sync.aligned.m16n8k16.row.col.f32.f16.f16.f32 "
        "{%0,%1,%2,%3}, {%4,%5,%6,%7}, {%8,%9}, {%10,%11,%12,%13};\n"
        : "=f"(d[0]), "=f"(d[1]), "=f"(d[2]), "=f"(d[3])
        : "r"(a[0]), "r"(a[1]), "r"(a[2]), "r"(a[3]),
          "r"(b[0]), "r"(b[1]),
          "f"(c[0]), "f"(c[1]), "f"(c[2]), "f"(c[3]));
}

__device__ __forceinline__ void ldsm_x4(uint32_t r[4], uint32_t saddr) {
    asm volatile(
        "ldmatrix.sync.aligned.m8n8.x4.shared.b16 {%0,%1,%2,%3}, [%4];"
        : "=r"(r[0]), "=r"(r[1]), "=r"(r[2]), "=r"(r[3]) : "r"(saddr));
}

// exact 2-term fp16 split of a float2
__device__ __forceinline__ void split2h(float2 v, uint32_t& hi, uint32_t& lo) {
    __half2 h = __float22half2_rn(v);
    hi = *(uint32_t*)&h;
    float2 r;
    r.x = v.x - __half2float(__low2half(h));
    r.y = v.y - __half2float(__high2half(h));
    __half2 l = __float22half2_rn(r);
    lo = *(uint32_t*)&l;
}

// ---------------- hyperA: p2 = tanh(tanh(t*W1+b1) @ W2 + b2) -------------------
// grid 64 x 256: 8 outputs per block, 32-way k-split (16-deep chains).
__global__ void hyperA_kernel(const float* __restrict__ t,
                              const float* __restrict__ W1,
                              const float* __restrict__ b1,
                              const float* __restrict__ W2,
                              const float* __restrict__ b2) {
    __shared__ float p1[HID];
    __shared__ float red[32][8];
    const int tid = threadIdx.x;
    float tv = t[0];
    for (int k = tid; k < HID; k += 256)
        p1[k] = tanhf(tv * W1[k] + b1[k]);
    __syncthreads();
    const int x = tid & 7, y = tid >> 3;       // x: output, y: k-split
    const int j = blockIdx.x * 8 + x;
    float acc = 0.0f;
#pragma unroll
    for (int i = 0; i < 16; i++) {
        int k = y + 32 * i;
        acc = fmaf(p1[k], W2[(size_t)k * HID + j], acc);
    }
    red[y][x] = acc;
    __syncthreads();
    if (tid < 8) {
        float s = b2[blockIdx.x * 8 + tid];
#pragma unroll
        for (int yy = 0; yy < 32; yy++) s += red[yy][tid];
        g_p2[blockIdx.x * 8 + tid] = tanhf(s);
    }
}

// ---------------- hyperB: p3 = p2 @ W3 + b3 ------------------------------------
// grid 386 x 512: 32 outputs per block, 16-way k-split (32-deep chains).
__global__ void hyperB_kernel(const float* __restrict__ W3,
                              const float* __restrict__ b3) {
    __shared__ float s2[HID];
    __shared__ float red[16][33];
    const int tid = threadIdx.x;
    if (tid < HID) s2[tid] = g_p2[tid];
    __syncthreads();
    const int x = tid & 31, y = tid >> 5;      // x: output, y: k-split
    const int j = blockIdx.x * 32 + x;
    const bool ok = j < NP;
    float acc = 0.0f;
    if (ok) {
#pragma unroll
        for (int i = 0; i < 32; i++) {
            int k = y + 16 * i;
            acc = fmaf(s2[k], W3[(size_t)k * NP + j], acc);
        }
    }
    red[y][x] = acc;
    __syncthreads();
    if (y == 0 && ok) {
        float s = b3[j];
#pragma unroll
        for (int yy = 0; yy < 16; yy++) s += red[yy][x];
        g_p3[j] = s;
    }
}

// ---------------- hyper3: param prep (fp16, d-permuted) -------------------------
// frag position f = 8b + 2t + i  <->  original col dd = 4t + 2b + i  (within 16)
__global__ void hyper3_kernel() {
    __shared__ float prod[WIDTH];
    int w = blockIdx.x, d = threadIdx.x;
    int idx = w * D_ + d;
    float Wv = g_p3[idx];
    float gv = g_p3[2 * BLOCK_P + idx];
    float Uv = g_p3[BLOCK_P + idx] * (1.0f / (1.0f + __expf(-gv)));

    // inverse permutation: original col d -> fragment position dp
    int dd = d & 15;
    int f = ((dd >> 1) & 1) * 8 + (dd >> 2) * 2 + (dd & 1);
    int dp = (d & ~15) | f;

    g_wh16[w * D_ + dp] = __float2half_rn(Wv);      // permute W's d-columns
    g_uth16[dp * WIDTH + w] = __float2half_rn(Uv);  // permute Ut's d-rows

    prod[d] = Wv * Uv;
    __syncthreads();
    if (d == 0) {
        float s = 0.0f;
#pragma unroll
        for (int k = 0; k < D_; k++) s += prod[k];
        g_wu[w] = s;
    }
    if (w == 0) g_B[d] = g_p3[3 * BLOCK_P + d];
}

// ---------------- main batch kernel --------------------------------------------
// CTA = 128 threads = 4 warps; warp = 16 rows (one m16 tile); grid = 8192.
__global__ __launch_bounds__(128, 6)
void cnf_mma_kernel(const float* __restrict__ z, float* __restrict__ out) {
    __shared__ __align__(16) uint8_t sWh[WIDTH * SROW];
    __shared__ __align__(16) uint8_t sUth[WIDTH * SROW];
    __shared__ float sB[WIDTH];
    __shared__ float swu[WIDTH];

    const int tid = threadIdx.x;

    // stage weights (128B global rows -> 144B pitch smem)
    {
        const uint4* s0 = (const uint4*)g_wh16;
        const uint4* s1 = (const uint4*)g_uth16;
#pragma unroll
        for (int i = tid; i < 512; i += 128) {
            int r = i >> 3, c = i & 7;
            int dst = r * SROW + c * 16;
            *(uint4*)(sWh + dst)  = s0[i];
            *(uint4*)(sUth + dst) = s1[i];
        }
        if (tid < WIDTH) { sB[tid] = g_B[tid]; swu[tid] = g_wu[tid]; }
    }
    __syncthreads();

    const int lane = tid & 31;
    const int warp = tid >> 5;
    const int g = lane >> 2;     // group (row within 8)
    const int t = lane & 3;      // thread in group
    const int rrow = lane & 7;   // ldmatrix row provider
    const int qq = lane >> 3;    // ldmatrix matrix id

    const uint32_t baseWh  = smem_u32(sWh);
    const uint32_t baseUth = smem_u32(sUth);
    const float inv = 1.0f / (float)WIDTH;

    const size_t r0 = (size_t)blockIdx.x * 64 + (size_t)warp * 16 + g;

    // ---- load z rows r0, r0+8 as float4 -> exact fp16 2-term A frags ----------
    uint32_t zh[4][4], zl[4][4];
    {
        const float4* zr0 = (const float4*)(z + r0 * D_);
        const float4* zr1 = (const float4*)(z + (r0 + 8) * D_);
#pragma unroll
        for (int kt = 0; kt < 4; kt++) {
            float4 v0 = zr0[4 * kt + t];
            float4 v1 = zr1[4 * kt + t];
            split2h(make_float2(v0.x, v0.y), zh[kt][0], zl[kt][0]);
            split2h(make_float2(v1.x, v1.y), zh[kt][1], zl[kt][1]);
            split2h(make_float2(v0.z, v0.w), zh[kt][2], zl[kt][2]);
            split2h(make_float2(v1.z, v1.w), zh[kt][3], zl[kt][3]);
        }
    }

    // ---- GEMM1: S = (zh + zl) * Wh ---------------------------------------------
    float S[8][4];
#pragma unroll
    for (int n = 0; n < 8; n++) {
        const uint32_t off = (uint32_t)((8 * n + rrow) * SROW + qq * 16);
        uint32_t bh[8];
        ldsm_x4(&bh[0], baseWh + off);
        ldsm_x4(&bh[4], baseWh + off + 64);
#pragma unroll
        for (int i = 0; i < 4; i++) S[n][i] = 0.0f;
#pragma unroll
        for (int kt = 0; kt < 4; kt++) {
            mma_f16(S[n], zh[kt], &bh[2 * kt], S[n]);
            mma_f16(S[n], zl[kt], &bh[2 * kt], S[n]);
        }
    }

    // ---- epilogue: h = tanh(S+B), trace, exact fp16 split into A2 frags --------
    uint32_t hh[4][4], hl[4][4];
    float tr0 = 0.0f, tr1 = 0.0f;
#pragma unroll
    for (int n = 0; n < 8; n++) {
        float2 bb = *(const float2*)&sB[8 * n + 2 * t];
        float2 ww = *(const float2*)&swu[8 * n + 2 * t];
        float h0 = fast_tanh(S[n][0] + bb.x);
        float h1 = fast_tanh(S[n][1] + bb.y);
        float h2 = fast_tanh(S[n][2] + bb.x);
        float h3 = fast_tanh(S[n][3] + bb.y);
        tr0 = fmaf(1.0f - h0 * h0, ww.x, tr0);
        tr0 = fmaf(1.0f - h1 * h1, ww.y, tr0);
        tr1 = fmaf(1.0f - h2 * h2, ww.x, tr1);
        tr1 = fmaf(1.0f - h3 * h3, ww.y, tr1);
        int kt = n >> 1;
        int o = (n & 1) ? 2 : 0;
        split2h(make_float2(h0, h1), hh[kt][o],     hl[kt][o]);
        split2h(make_float2(h2, h3), hh[kt][o + 1], hl[kt][o + 1]);
    }

    // ---- GEMM2: DZ = (hh + hl) * Uth --------------------------------------------
    float DZ[8][4];
#pragma unroll
    for (int n = 0; n < 8; n++) {
        const uint32_t off = (uint32_t)((8 * n + rrow) * SROW + qq * 16);
        uint32_t bh[8];
        ldsm_x4(&bh[0], baseUth + off);
        ldsm_x4(&bh[4], baseUth + off + 64);
#pragma unroll
        for (int i = 0; i < 4; i++) DZ[n][i] = 0.0f;
#pragma unroll
        for (int kt = 0; kt < 4; kt++) {
            mma_f16(DZ[n], hh[kt], &bh[2 * kt], DZ[n]);
            mma_f16(DZ[n], hl[kt], &bh[2 * kt], DZ[n]);
        }
    }

    // ---- store dz/64 as float4 ----------------------------------------------------
#pragma unroll
    for (int j = 0; j < 4; j++) {
        int col = 16 * j + 4 * t;
        *(float4*)(out + r0 * D_ + col) =
            make_float4(DZ[2 * j][0] * inv, DZ[2 * j][1] * inv,
                        DZ[2 * j + 1][0] * inv, DZ[2 * j + 1][1] * inv);
        *(float4*)(out + (r0 + 8) * D_ + col) =
            make_float4(DZ[2 * j][2] * inv, DZ[2 * j][3] * inv,
                        DZ[2 * j + 1][2] * inv, DZ[2 * j + 1][3] * inv);
    }

    // ---- trace: reduce over quad, write -tr/64 -------------------------------------
    tr0 += __shfl_xor_sync(0xFFFFFFFFu, tr0, 1);
    tr0 += __shfl_xor_sync(0xFFFFFFFFu, tr0, 2);
    tr1 += __shfl_xor_sync(0xFFFFFFFFu, tr1, 1);
    tr1 += __shfl_xor_sync(0xFFFFFFFFu, tr1, 2);
    if (t == 0) out[(size_t)BATCH * D_ + r0] = -tr0 * inv;
    if (t == 1) out[(size_t)BATCH * D_ + r0 + 8] = -tr1 * inv;
}

// ---------------------------------------------------------------------------
extern "C" void kernel_launch(void* const* d_in, const int* in_sizes, int n_in,
                              void* d_out, int out_size) {
    const float* t  = (const float*)d_in[0];
    const float* z  = (const float*)d_in[1];
    const float* W1 = (const float*)d_in[3];
    const float* b1 = (const float*)d_in[4];
    const float* W2 = (const float*)d_in[5];
    const float* b2 = (const float*)d_in[6];
    const float* W3 = (const float*)d_in[7];
    const float* b3 = (const float*)d_in[8];
    float* out = (float*)d_out;

    hyperA_kernel<<<64, 256>>>(t, W1, b1, W2, b2);
    hyperB_kernel<<<(NP + 31) / 32, 512>>>(W3, b3);
    hyper3_kernel<<<WIDTH, D_>>>();
    cnf_mma_kernel<<<BATCH / 64, 128>>>(z, out);
}

// round 9
// speedup vs baseline: 1.6105x; 1.0362x over previous
#include <cuda_runtime.h>
#include <cuda_fp16.h>
#include <cstdint>

// ---------------------------------------------------------------------------
// CNF_59133109731627 — round 9: R7 main kernel (natural 96 regs, best measured)
// + R8 wide-split hypernet kernels. Pure recomposition of measured-best parts.
// ---------------------------------------------------------------------------

#define D_      64
#define HID     512
#define WIDTH   64
#define BATCH   524288
#define BLOCK_P (WIDTH * D_)            // 4096
#define NP      (3 * BLOCK_P + WIDTH)   // 12352
#define SROW    144                     // padded smem row pitch (bytes)

// ---------------- device scratch ---------------------------------------------
__device__ float g_p2[HID];
__device__ float g_p3[NP];
__device__ __align__(16) __half g_wh16[BLOCK_P];    // W  [w][dp] fp16 (d-cols permuted)
__device__ __align__(16) __half g_uth16[BLOCK_P];   // U^T[dp][w] fp16 (d-rows permuted)
__device__ float g_B[WIDTH];
__device__ float g_wu[WIDTH];

// ---------------- helpers -----------------------------------------------------
__device__ __forceinline__ float fast_tanh(float x) {
    float e = __expf(2.0f * x);
    return 1.0f - __fdividef(2.0f, e + 1.0f);
}

__device__ __forceinline__ uint32_t smem_u32(const void* p) {
    uint32_t a;
    asm("{ .reg .u64 t; cvta.to.shared.u64 t, %1; cvt.u32.u64 %0, t; }"
        : "=r"(a) : "l"(p));
    return a;
}

__device__ __forceinline__ void mma_f16(float d[4], const uint32_t a[4],
                                        const uint32_t b[2], const float c[4]) {
    asm volatile(
        "mma.sync.aligned.m16n8k16.row.col.f32.f16.f16.f32 "
        "{%0,%1,%2,%3}, {%4,%5,%6,%7}, {%8,%9}, {%10,%11,%12,%13};\n"
        : "=f"(d[0]), "=f"(d[1]), "=f"(d[2]), "=f"(d[3])
        : "r"(a[0]), "r"(a[1]), "r"(a[2]), "r"(a[3]),
          "r"(b[0]), "r"(b[1]),
          "f"(c[0]), "f"(c[1]), "f"(c[2]), "f"(c[3]));
}

__device__ __forceinline__ void ldsm_x4(uint32_t r[4], uint32_t saddr) {
    asm volatile(
        "ldmatrix.sync.aligned.m8n8.x4.shared.b16 {%0,%1,%2,%3}, [%4];"
        : "=r"(r[0]), "=r"(r[1]), "=r"(r[2]), "=r"(r[3]) : "r"(saddr));
}

// exact 2-term fp16 split of a float2
__device__ __forceinline__ void split2h(float2 v, uint32_t& hi, uint32_t& lo) {
    __half2 h = __float22half2_rn(v);
    hi = *(uint32_t*)&h;
    float2 r;
    r.x = v.x - __half2float(__low2half(h));
    r.y = v.y - __half2float(__high2half(h));
    __half2 l = __float22half2_rn(r);
    lo = *(uint32_t*)&l;
}

// ---------------- hyperA: p2 = tanh(tanh(t*W1+b1) @ W2 + b2) -------------------
// grid 64 x 256: 8 outputs per block, 32-way k-split (16-deep chains).
__global__ void hyperA_kernel(const float* __restrict__ t,
                              const float* __restrict__ W1,
                              const float* __restrict__ b1,
                              const float* __restrict__ W2,
                              const float* __restrict__ b2) {
    __shared__ float p1[HID];
    __shared__ float red[32][8];
    const int tid = threadIdx.x;
    float tv = t[0];
    for (int k = tid; k < HID; k += 256)
        p1[k] = tanhf(tv * W1[k] + b1[k]);
    __syncthreads();
    const int x = tid & 7, y = tid >> 3;       // x: output, y: k-split
    const int j = blockIdx.x * 8 + x;
    float acc = 0.0f;
#pragma unroll
    for (int i = 0; i < 16; i++) {
        int k = y + 32 * i;
        acc = fmaf(p1[k], W2[(size_t)k * HID + j], acc);
    }
    red[y][x] = acc;
    __syncthreads();
    if (tid < 8) {
        float s = b2[blockIdx.x * 8 + tid];
#pragma unroll
        for (int yy = 0; yy < 32; yy++) s += red[yy][tid];
        g_p2[blockIdx.x * 8 + tid] = tanhf(s);
    }
}

// ---------------- hyperB: p3 = p2 @ W3 + b3 ------------------------------------
// grid 386 x 512: 32 outputs per block, 16-way k-split (32-deep chains).
__global__ void hyperB_kernel(const float* __restrict__ W3,
                              const float* __restrict__ b3) {
    __shared__ float s2[HID];
    __shared__ float red[16][33];
    const int tid = threadIdx.x;
    if (tid < HID) s2[tid] = g_p2[tid];
    __syncthreads();
    const int x = tid & 31, y = tid >> 5;      // x: output, y: k-split
    const int j = blockIdx.x * 32 + x;
    const bool ok = j < NP;
    float acc = 0.0f;
    if (ok) {
#pragma unroll
        for (int i = 0; i < 32; i++) {
            int k = y + 16 * i;
            acc = fmaf(s2[k], W3[(size_t)k * NP + j], acc);
        }
    }
    red[y][x] = acc;
    __syncthreads();
    if (y == 0 && ok) {
        float s = b3[j];
#pragma unroll
        for (int yy = 0; yy < 16; yy++) s += red[yy][x];
        g_p3[j] = s;
    }
}

// ---------------- hyper3: param prep (fp16, d-permuted) -------------------------
// frag position f = 8b + 2t + i  <->  original col dd = 4t + 2b + i  (within 16)
__global__ void hyper3_kernel() {
    __shared__ float prod[WIDTH];
    int w = blockIdx.x, d = threadIdx.x;
    int idx = w * D_ + d;
    float Wv = g_p3[idx];
    float gv = g_p3[2 * BLOCK_P + idx];
    float Uv = g_p3[BLOCK_P + idx] * (1.0f / (1.0f + __expf(-gv)));

    // inverse permutation: original col d -> fragment position dp
    int dd = d & 15;
    int f = ((dd >> 1) & 1) * 8 + (dd >> 2) * 2 + (dd & 1);
    int dp = (d & ~15) | f;

    g_wh16[w * D_ + dp] = __float2half_rn(Wv);      // permute W's d-columns
    g_uth16[dp * WIDTH + w] = __float2half_rn(Uv);  // permute Ut's d-rows

    prod[d] = Wv * Uv;
    __syncthreads();
    if (d == 0) {
        float s = 0.0f;
#pragma unroll
        for (int k = 0; k < D_; k++) s += prod[k];
        g_wu[w] = s;
    }
    if (w == 0) g_B[d] = g_p3[3 * BLOCK_P + d];
}

// ---------------- main batch kernel --------------------------------------------
// CTA = 128 threads = 4 warps; warp = 16 rows (one m16 tile); grid = 8192.
__global__ __launch_bounds__(128)
void cnf_mma_kernel(const float* __restrict__ z, float* __restrict__ out) {
    __shared__ __align__(16) uint8_t sWh[WIDTH * SROW];
    __shared__ __align__(16) uint8_t sUth[WIDTH * SROW];
    __shared__ float sB[WIDTH];
    __shared__ float swu[WIDTH];

    const int tid = threadIdx.x;

    // stage weights (128B global rows -> 144B pitch smem)
    {
        const uint4* s0 = (const uint4*)g_wh16;
        const uint4* s1 = (const uint4*)g_uth16;
#pragma unroll
        for (int i = tid; i < 512; i += 128) {
            int r = i >> 3, c = i & 7;
            int dst = r * SROW + c * 16;
            *(uint4*)(sWh + dst)  = s0[i];
            *(uint4*)(sUth + dst) = s1[i];
        }
        if (tid < WIDTH) { sB[tid] = g_B[tid]; swu[tid] = g_wu[tid]; }
    }
    __syncthreads();

    const int lane = tid & 31;
    const int warp = tid >> 5;
    const int g = lane >> 2;     // group (row within 8)
    const int t = lane & 3;      // thread in group
    const int rrow = lane & 7;   // ldmatrix row provider
    const int qq = lane >> 3;    // ldmatrix matrix id

    const uint32_t baseWh  = smem_u32(sWh);
    const uint32_t baseUth = smem_u32(sUth);
    const float inv = 1.0f / (float)WIDTH;

    const size_t r0 = (size_t)blockIdx.x * 64 + (size_t)warp * 16 + g;

    // ---- load z rows r0, r0+8 as float4 -> exact fp16 2-term A frags ----------
    uint32_t zh[4][4], zl[4][4];
    {
        const float4* zr0 = (const float4*)(z + r0 * D_);
        const float4* zr1 = (const float4*)(z + (r0 + 8) * D_);
#pragma unroll
        for (int kt = 0; kt < 4; kt++) {
            float4 v0 = zr0[4 * kt + t];
            float4 v1 = zr1[4 * kt + t];
            split2h(make_float2(v0.x, v0.y), zh[kt][0], zl[kt][0]);
            split2h(make_float2(v1.x, v1.y), zh[kt][1], zl[kt][1]);
            split2h(make_float2(v0.z, v0.w), zh[kt][2], zl[kt][2]);
            split2h(make_float2(v1.z, v1.w), zh[kt][3], zl[kt][3]);
        }
    }

    // ---- GEMM1: S = (zh + zl) * Wh ---------------------------------------------
    float S[8][4];
#pragma unroll
    for (int n = 0; n < 8; n++) {
        const uint32_t off = (uint32_t)((8 * n + rrow) * SROW + qq * 16);
        uint32_t bh[8];
        ldsm_x4(&bh[0], baseWh + off);
        ldsm_x4(&bh[4], baseWh + off + 64);
#pragma unroll
        for (int i = 0; i < 4; i++) S[n][i] = 0.0f;
#pragma unroll
        for (int kt = 0; kt < 4; kt++) {
            mma_f16(S[n], zh[kt], &bh[2 * kt], S[n]);
            mma_f16(S[n], zl[kt], &bh[2 * kt], S[n]);
        }
    }

    // ---- epilogue: h = tanh(S+B), trace, exact fp16 split into A2 frags --------
    uint32_t hh[4][4], hl[4][4];
    float tr0 = 0.0f, tr1 = 0.0f;
#pragma unroll
    for (int n = 0; n < 8; n++) {
        float2 bb = *(const float2*)&sB[8 * n + 2 * t];
        float2 ww = *(const float2*)&swu[8 * n + 2 * t];
        float h0 = fast_tanh(S[n][0] + bb.x);
        float h1 = fast_tanh(S[n][1] + bb.y);
        float h2 = fast_tanh(S[n][2] + bb.x);
        float h3 = fast_tanh(S[n][3] + bb.y);
        tr0 = fmaf(1.0f - h0 * h0, ww.x, tr0);
        tr0 = fmaf(1.0f - h1 * h1, ww.y, tr0);
        tr1 = fmaf(1.0f - h2 * h2, ww.x, tr1);
        tr1 = fmaf(1.0f - h3 * h3, ww.y, tr1);
        int kt = n >> 1;
        int o = (n & 1) ? 2 : 0;
        split2h(make_float2(h0, h1), hh[kt][o],     hl[kt][o]);
        split2h(make_float2(h2, h3), hh[kt][o + 1], hl[kt][o + 1]);
    }

    // ---- GEMM2: DZ = (hh + hl) * Uth --------------------------------------------
    float DZ[8][4];
#pragma unroll
    for (int n = 0; n < 8; n++) {
        const uint32_t off = (uint32_t)((8 * n + rrow) * SROW + qq * 16);
        uint32_t bh[8];
        ldsm_x4(&bh[0], baseUth + off);
        ldsm_x4(&bh[4], baseUth + off + 64);
#pragma unroll
        for (int i = 0; i < 4; i++) DZ[n][i] = 0.0f;
#pragma unroll
        for (int kt = 0; kt < 4; kt++) {
            mma_f16(DZ[n], hh[kt], &bh[2 * kt], DZ[n]);
            mma_f16(DZ[n], hl[kt], &bh[2 * kt], DZ[n]);
        }
    }

    // ---- store dz/64 as float4 ----------------------------------------------------
#pragma unroll
    for (int j = 0; j < 4; j++) {
        int col = 16 * j + 4 * t;
        *(float4*)(out + r0 * D_ + col) =
            make_float4(DZ[2 * j][0] * inv, DZ[2 * j][1] * inv,
                        DZ[2 * j + 1][0] * inv, DZ[2 * j + 1][1] * inv);
        *(float4*)(out + (r0 + 8) * D_ + col) =
            make_float4(DZ[2 * j][2] * inv, DZ[2 * j][3] * inv,
                        DZ[2 * j + 1][2] * inv, DZ[2 * j + 1][3] * inv);
    }

    // ---- trace: reduce over quad, write -tr/64 -------------------------------------
    tr0 += __shfl_xor_sync(0xFFFFFFFFu, tr0, 1);
    tr0 += __shfl_xor_sync(0xFFFFFFFFu, tr0, 2);
    tr1 += __shfl_xor_sync(0xFFFFFFFFu, tr1, 1);
    tr1 += __shfl_xor_sync(0xFFFFFFFFu, tr1, 2);
    if (t == 0) out[(size_t)BATCH * D_ + r0] = -tr0 * inv;
    if (t == 1) out[(size_t)BATCH * D_ + r0 + 8] = -tr1 * inv;
}

// ---------------------------------------------------------------------------
extern "C" void kernel_launch(void* const* d_in, const int* in_sizes, int n_in,
                              void* d_out, int out_size) {
    const float* t  = (const float*)d_in[0];
    const float* z  = (const float*)d_in[1];
    const float* W1 = (const float*)d_in[3];
    const float* b1 = (const float*)d_in[4];
    const float* W2 = (const float*)d_in[5];
    const float* b2 = (const float*)d_in[6];
    const float* W3 = (const float*)d_in[7];
    const float* b3 = (const float*)d_in[8];
    float* out = (float*)d_out;

    hyperA_kernel<<<64, 256>>>(t, W1, b1, W2, b2);
    hyperB_kernel<<<(NP + 31) / 32, 512>>>(W3, b3);
    hyper3_kernel<<<WIDTH, D_>>>();
    cnf_mma_kernel<<<BATCH / 64, 128>>>(z, out);
}

// round 10
// speedup vs baseline: 1.7847x; 1.1081x over previous
#include <cuda_runtime.h>
#include <cuda_fp16.h>
#include <cstdint>

// ---------------------------------------------------------------------------
// CNF_59133109731627 — round 10: plain fp16 single-pass MMA (drop lo-term
// passes; error budget ~4.4e-4 vs 1e-3 gate). Halves MMA count, removes all
// split-residual math, shrinks registers for a free occupancy jump.
// ---------------------------------------------------------------------------

#define D_      64
#define HID     512
#define WIDTH   64
#define BATCH   524288
#define BLOCK_P (WIDTH * D_)            // 4096
#define NP      (3 * BLOCK_P + WIDTH)   // 12352
#define SROW    144                     // padded smem row pitch (bytes)

// ---------------- device scratch ---------------------------------------------
__device__ float g_p2[HID];
__device__ float g_p3[NP];
__device__ __align__(16) __half g_wh16[BLOCK_P];    // W  [w][dp] fp16 (d-cols permuted)
__device__ __align__(16) __half g_uth16[BLOCK_P];   // U^T[dp][w] fp16 (d-rows permuted)
__device__ float g_B[WIDTH];
__device__ float g_wu[WIDTH];

// ---------------- helpers -----------------------------------------------------
__device__ __forceinline__ float fast_tanh(float x) {
    float e = __expf(2.0f * x);
    return 1.0f - __fdividef(2.0f, e + 1.0f);
}

__device__ __forceinline__ uint32_t smem_u32(const void* p) {
    uint32_t a;
    asm("{ .reg .u64 t; cvta.to.shared.u64 t, %1; cvt.u32.u64 %0, t; }"
        : "=r"(a) : "l"(p));
    return a;
}

__device__ __forceinline__ void mma_f16(float d[4], const uint32_t a[4],
                                        const uint32_t b[2], const float c[4]) {
    asm volatile(
        "mma.sync.aligned.m16n8k16.row.col.f32.f16.f16.f32 "
        "{%0,%1,%2,%3}, {%4,%5,%6,%7}, {%8,%9}, {%10,%11,%12,%13};\n"
        : "=f"(d[0]), "=f"(d[1]), "=f"(d[2]), "=f"(d[3])
        : "r"(a[0]), "r"(a[1]), "r"(a[2]), "r"(a[3]),
          "r"(b[0]), "r"(b[1]),
          "f"(c[0]), "f"(c[1]), "f"(c[2]), "f"(c[3]));
}

__device__ __forceinline__ void ldsm_x4(uint32_t r[4], uint32_t saddr) {
    asm volatile(
        "ldmatrix.sync.aligned.m8n8.x4.shared.b16 {%0,%1,%2,%3}, [%4];"
        : "=r"(r[0]), "=r"(r[1]), "=r"(r[2]), "=r"(r[3]) : "r"(saddr));
}

__device__ __forceinline__ uint32_t pack_h2(float2 v) {
    __half2 h = __float22half2_rn(v);
    return *(uint32_t*)&h;
}

// ---------------- hyperA: p2 = tanh(tanh(t*W1+b1) @ W2 + b2) -------------------
// grid 64 x 256: 8 outputs per block, 32-way k-split (16-deep chains).
__global__ void hyperA_kernel(const float* __restrict__ t,
                              const float* __restrict__ W1,
                              const float* __restrict__ b1,
                              const float* __restrict__ W2,
                              const float* __restrict__ b2) {
    __shared__ float p1[HID];
    __shared__ float red[32][8];
    const int tid = threadIdx.x;
    float tv = t[0];
    for (int k = tid; k < HID; k += 256)
        p1[k] = tanhf(tv * W1[k] + b1[k]);
    __syncthreads();
    const int x = tid & 7, y = tid >> 3;       // x: output, y: k-split
    const int j = blockIdx.x * 8 + x;
    float acc = 0.0f;
#pragma unroll
    for (int i = 0; i < 16; i++) {
        int k = y + 32 * i;
        acc = fmaf(p1[k], W2[(size_t)k * HID + j], acc);
    }
    red[y][x] = acc;
    __syncthreads();
    if (tid < 8) {
        float s = b2[blockIdx.x * 8 + tid];
#pragma unroll
        for (int yy = 0; yy < 32; yy++) s += red[yy][tid];
        g_p2[blockIdx.x * 8 + tid] = tanhf(s);
    }
}

// ---------------- hyperB: p3 = p2 @ W3 + b3 ------------------------------------
// grid 386 x 512: 32 outputs per block, 16-way k-split (32-deep chains).
__global__ void hyperB_kernel(const float* __restrict__ W3,
                              const float* __restrict__ b3) {
    __shared__ float s2[HID];
    __shared__ float red[16][33];
    const int tid = threadIdx.x;
    if (tid < HID) s2[tid] = g_p2[tid];
    __syncthreads();
    const int x = tid & 31, y = tid >> 5;      // x: output, y: k-split
    const int j = blockIdx.x * 32 + x;
    const bool ok = j < NP;
    float acc = 0.0f;
    if (ok) {
#pragma unroll
        for (int i = 0; i < 32; i++) {
            int k = y + 16 * i;
            acc = fmaf(s2[k], W3[(size_t)k * NP + j], acc);
        }
    }
    red[y][x] = acc;
    __syncthreads();
    if (y == 0 && ok) {
        float s = b3[j];
#pragma unroll
        for (int yy = 0; yy < 16; yy++) s += red[yy][x];
        g_p3[j] = s;
    }
}

// ---------------- hyper3: param prep (fp16, d-permuted) -------------------------
// frag position f = 8b + 2t + i  <->  original col dd = 4t + 2b + i  (within 16)
__global__ void hyper3_kernel() {
    __shared__ float prod[WIDTH];
    int w = blockIdx.x, d = threadIdx.x;
    int idx = w * D_ + d;
    float Wv = g_p3[idx];
    float gv = g_p3[2 * BLOCK_P + idx];
    float Uv = g_p3[BLOCK_P + idx] * (1.0f / (1.0f + __expf(-gv)));

    // inverse permutation: original col d -> fragment position dp
    int dd = d & 15;
    int f = ((dd >> 1) & 1) * 8 + (dd >> 2) * 2 + (dd & 1);
    int dp = (d & ~15) | f;

    g_wh16[w * D_ + dp] = __float2half_rn(Wv);      // permute W's d-columns
    g_uth16[dp * WIDTH + w] = __float2half_rn(Uv);  // permute Ut's d-rows

    prod[d] = Wv * Uv;
    __syncthreads();
    if (d == 0) {
        float s = 0.0f;
#pragma unroll
        for (int k = 0; k < D_; k++) s += prod[k];
        g_wu[w] = s;
    }
    if (w == 0) g_B[d] = g_p3[3 * BLOCK_P + d];
}

// ---------------- main batch kernel --------------------------------------------
// CTA = 128 threads = 4 warps; warp = 16 rows (one m16 tile); grid = 8192.
__global__ __launch_bounds__(128)
void cnf_mma_kernel(const float* __restrict__ z, float* __restrict__ out) {
    __shared__ __align__(16) uint8_t sWh[WIDTH * SROW];
    __shared__ __align__(16) uint8_t sUth[WIDTH * SROW];
    __shared__ float sB[WIDTH];
    __shared__ float swu[WIDTH];

    const int tid = threadIdx.x;

    // stage weights (128B global rows -> 144B pitch smem)
    {
        const uint4* s0 = (const uint4*)g_wh16;
        const uint4* s1 = (const uint4*)g_uth16;
#pragma unroll
        for (int i = tid; i < 512; i += 128) {
            int r = i >> 3, c = i & 7;
            int dst = r * SROW + c * 16;
            *(uint4*)(sWh + dst)  = s0[i];
            *(uint4*)(sUth + dst) = s1[i];
        }
        if (tid < WIDTH) { sB[tid] = g_B[tid]; swu[tid] = g_wu[tid]; }
    }
    __syncthreads();

    const int lane = tid & 31;
    const int warp = tid >> 5;
    const int g = lane >> 2;     // group (row within 8)
    const int t = lane & 3;      // thread in group
    const int rrow = lane & 7;   // ldmatrix row provider
    const int qq = lane >> 3;    // ldmatrix matrix id

    const uint32_t baseWh  = smem_u32(sWh);
    const uint32_t baseUth = smem_u32(sUth);
    const float inv = 1.0f / (float)WIDTH;

    const size_t r0 = (size_t)blockIdx.x * 64 + (size_t)warp * 16 + g;

    // ---- load z rows r0, r0+8 as float4 -> fp16 A frags -----------------------
    uint32_t zh[4][4];
    {
        const float4* zr0 = (const float4*)(z + r0 * D_);
        const float4* zr1 = (const float4*)(z + (r0 + 8) * D_);
#pragma unroll
        for (int kt = 0; kt < 4; kt++) {
            float4 v0 = zr0[4 * kt + t];
            float4 v1 = zr1[4 * kt + t];
            zh[kt][0] = pack_h2(make_float2(v0.x, v0.y));
            zh[kt][1] = pack_h2(make_float2(v1.x, v1.y));
            zh[kt][2] = pack_h2(make_float2(v0.z, v0.w));
            zh[kt][3] = pack_h2(make_float2(v1.z, v1.w));
        }
    }

    // ---- GEMM1: S = zh * Wh -----------------------------------------------------
    float S[8][4];
#pragma unroll
    for (int n = 0; n < 8; n++) {
        const uint32_t off = (uint32_t)((8 * n + rrow) * SROW + qq * 16);
        uint32_t bh[8];
        ldsm_x4(&bh[0], baseWh + off);
        ldsm_x4(&bh[4], baseWh + off + 64);
#pragma unroll
        for (int i = 0; i < 4; i++) S[n][i] = 0.0f;
#pragma unroll
        for (int kt = 0; kt < 4; kt++)
            mma_f16(S[n], zh[kt], &bh[2 * kt], S[n]);
    }

    // ---- epilogue: h = tanh(S+B), trace, fp16 A2 frags ---------------------------
    uint32_t hh[4][4];
    float tr0 = 0.0f, tr1 = 0.0f;
#pragma unroll
    for (int n = 0; n < 8; n++) {
        float2 bb = *(const float2*)&sB[8 * n + 2 * t];
        float2 ww = *(const float2*)&swu[8 * n + 2 * t];
        float h0 = fast_tanh(S[n][0] + bb.x);
        float h1 = fast_tanh(S[n][1] + bb.y);
        float h2 = fast_tanh(S[n][2] + bb.x);
        float h3 = fast_tanh(S[n][3] + bb.y);
        tr0 = fmaf(1.0f - h0 * h0, ww.x, tr0);
        tr0 = fmaf(1.0f - h1 * h1, ww.y, tr0);
        tr1 = fmaf(1.0f - h2 * h2, ww.x, tr1);
        tr1 = fmaf(1.0f - h3 * h3, ww.y, tr1);
        int kt = n >> 1;
        int o = (n & 1) ? 2 : 0;
        hh[kt][o]     = pack_h2(make_float2(h0, h1));
        hh[kt][o + 1] = pack_h2(make_float2(h2, h3));
    }

    // ---- GEMM2: DZ = hh * Uth -----------------------------------------------------
    float DZ[8][4];
#pragma unroll
    for (int n = 0; n < 8; n++) {
        const uint32_t off = (uint32_t)((8 * n + rrow) * SROW + qq * 16);
        uint32_t bh[8];
        ldsm_x4(&bh[0], baseUth + off);
        ldsm_x4(&bh[4], baseUth + off + 64);
#pragma unroll
        for (int i = 0; i < 4; i++) DZ[n][i] = 0.0f;
#pragma unroll
        for (int kt = 0; kt < 4; kt++)
            mma_f16(DZ[n], hh[kt], &bh[2 * kt], DZ[n]);
    }

    // ---- store dz/64 as float4 ------------------------------------------------------
#pragma unroll
    for (int j = 0; j < 4; j++) {
        int col = 16 * j + 4 * t;
        *(float4*)(out + r0 * D_ + col) =
            make_float4(DZ[2 * j][0] * inv, DZ[2 * j][1] * inv,
                        DZ[2 * j + 1][0] * inv, DZ[2 * j + 1][1] * inv);
        *(float4*)(out + (r0 + 8) * D_ + col) =
            make_float4(DZ[2 * j][2] * inv, DZ[2 * j][3] * inv,
                        DZ[2 * j + 1][2] * inv, DZ[2 * j + 1][3] * inv);
    }

    // ---- trace: reduce over quad, write -tr/64 ---------------------------------------
    tr0 += __shfl_xor_sync(0xFFFFFFFFu, tr0, 1);
    tr0 += __shfl_xor_sync(0xFFFFFFFFu, tr0, 2);
    tr1 += __shfl_xor_sync(0xFFFFFFFFu, tr1, 1);
    tr1 += __shfl_xor_sync(0xFFFFFFFFu, tr1, 2);
    if (t == 0) out[(size_t)BATCH * D_ + r0] = -tr0 * inv;
    if (t == 1) out[(size_t)BATCH * D_ + r0 + 8] = -tr1 * inv;
}

// ---------------------------------------------------------------------------
extern "C" void kernel_launch(void* const* d_in, const int* in_sizes, int n_in,
                              void* d_out, int out_size) {
    const float* t  = (const float*)d_in[0];
    const float* z  = (const float*)d_in[1];
    const float* W1 = (const float*)d_in[3];
    const float* b1 = (const float*)d_in[4];
    const float* W2 = (const float*)d_in[5];
    const float* b2 = (const float*)d_in[6];
    const float* W3 = (const float*)d_in[7];
    const float* b3 = (const float*)d_in[8];
    float* out = (float*)d_out;

    hyperA_kernel<<<64, 256>>>(t, W1, b1, W2, b2);
    hyperB_kernel<<<(NP + 31) / 32, 512>>>(W3, b3);
    hyper3_kernel<<<WIDTH, D_>>>();
    cnf_mma_kernel<<<BATCH / 64, 128>>>(z, out);
}

// round 11
// speedup vs baseline: 1.8817x; 1.0544x over previous
#include <cuda_runtime.h>
#include <cuda_fp16.h>
#include <cstdint>

// ---------------------------------------------------------------------------
// CNF_59133109731627 — round 11: single-pass fp16 MMA, 2 m-tiles per warp
// (32 rows per weight sweep) to halve ldmatrix L1 traffic per batch row.
// ---------------------------------------------------------------------------

#define D_      64
#define HID     512
#define WIDTH   64
#define BATCH   524288
#define BLOCK_P (WIDTH * D_)            // 4096
#define NP      (3 * BLOCK_P + WIDTH)   // 12352
#define SROW    144                     // padded smem row pitch (bytes)

// ---------------- device scratch ---------------------------------------------
__device__ float g_p2[HID];
__device__ float g_p3[NP];
__device__ __align__(16) __half g_wh16[BLOCK_P];    // W  [w][dp] fp16 (d-cols permuted)
__device__ __align__(16) __half g_uth16[BLOCK_P];   // U^T[dp][w] fp16 (d-rows permuted)
__device__ float g_B[WIDTH];
__device__ float g_wu[WIDTH];

// ---------------- helpers -----------------------------------------------------
__device__ __forceinline__ float fast_tanh(float x) {
    float e = __expf(2.0f * x);
    return 1.0f - __fdividef(2.0f, e + 1.0f);
}

__device__ __forceinline__ uint32_t smem_u32(const void* p) {
    uint32_t a;
    asm("{ .reg .u64 t; cvta.to.shared.u64 t, %1; cvt.u32.u64 %0, t; }"
        : "=r"(a) : "l"(p));
    return a;
}

__device__ __forceinline__ void mma_f16(float d[4], const uint32_t a[4],
                                        const uint32_t b[2], const float c[4]) {
    asm volatile(
        "mma.sync.aligned.m16n8k16.row.col.f32.f16.f16.f32 "
        "{%0,%1,%2,%3}, {%4,%5,%6,%7}, {%8,%9}, {%10,%11,%12,%13};\n"
        : "=f"(d[0]), "=f"(d[1]), "=f"(d[2]), "=f"(d[3])
        : "r"(a[0]), "r"(a[1]), "r"(a[2]), "r"(a[3]),
          "r"(b[0]), "r"(b[1]),
          "f"(c[0]), "f"(c[1]), "f"(c[2]), "f"(c[3]));
}

__device__ __forceinline__ void ldsm_x4(uint32_t r[4], uint32_t saddr) {
    asm volatile(
        "ldmatrix.sync.aligned.m8n8.x4.shared.b16 {%0,%1,%2,%3}, [%4];"
        : "=r"(r[0]), "=r"(r[1]), "=r"(r[2]), "=r"(r[3]) : "r"(saddr));
}

__device__ __forceinline__ uint32_t pack_h2(float2 v) {
    __half2 h = __float22half2_rn(v);
    return *(uint32_t*)&h;
}

// ---------------- hyperA: p2 = tanh(tanh(t*W1+b1) @ W2 + b2) -------------------
__global__ void hyperA_kernel(const float* __restrict__ t,
                              const float* __restrict__ W1,
                              const float* __restrict__ b1,
                              const float* __restrict__ W2,
                              const float* __restrict__ b2) {
    __shared__ float p1[HID];
    __shared__ float red[32][8];
    const int tid = threadIdx.x;
    float tv = t[0];
    for (int k = tid; k < HID; k += 256)
        p1[k] = tanhf(tv * W1[k] + b1[k]);
    __syncthreads();
    const int x = tid & 7, y = tid >> 3;
    const int j = blockIdx.x * 8 + x;
    float acc = 0.0f;
#pragma unroll
    for (int i = 0; i < 16; i++) {
        int k = y + 32 * i;
        acc = fmaf(p1[k], W2[(size_t)k * HID + j], acc);
    }
    red[y][x] = acc;
    __syncthreads();
    if (tid < 8) {
        float s = b2[blockIdx.x * 8 + tid];
#pragma unroll
        for (int yy = 0; yy < 32; yy++) s += red[yy][tid];
        g_p2[blockIdx.x * 8 + tid] = tanhf(s);
    }
}

// ---------------- hyperB: p3 = p2 @ W3 + b3 ------------------------------------
__global__ void hyperB_kernel(const float* __restrict__ W3,
                              const float* __restrict__ b3) {
    __shared__ float s2[HID];
    __shared__ float red[16][33];
    const int tid = threadIdx.x;
    if (tid < HID) s2[tid] = g_p2[tid];
    __syncthreads();
    const int x = tid & 31, y = tid >> 5;
    const int j = blockIdx.x * 32 + x;
    const bool ok = j < NP;
    float acc = 0.0f;
    if (ok) {
#pragma unroll
        for (int i = 0; i < 32; i++) {
            int k = y + 16 * i;
            acc = fmaf(s2[k], W3[(size_t)k * NP + j], acc);
        }
    }
    red[y][x] = acc;
    __syncthreads();
    if (y == 0 && ok) {
        float s = b3[j];
#pragma unroll
        for (int yy = 0; yy < 16; yy++) s += red[yy][x];
        g_p3[j] = s;
    }
}

// ---------------- hyper3: param prep (fp16, d-permuted) -------------------------
__global__ void hyper3_kernel() {
    __shared__ float prod[WIDTH];
    int w = blockIdx.x, d = threadIdx.x;
    int idx = w * D_ + d;
    float Wv = g_p3[idx];
    float gv = g_p3[2 * BLOCK_P + idx];
    float Uv = g_p3[BLOCK_P + idx] * (1.0f / (1.0f + __expf(-gv)));

    int dd = d & 15;
    int f = ((dd >> 1) & 1) * 8 + (dd >> 2) * 2 + (dd & 1);
    int dp = (d & ~15) | f;

    g_wh16[w * D_ + dp] = __float2half_rn(Wv);
    g_uth16[dp * WIDTH + w] = __float2half_rn(Uv);

    prod[d] = Wv * Uv;
    __syncthreads();
    if (d == 0) {
        float s = 0.0f;
#pragma unroll
        for (int k = 0; k < D_; k++) s += prod[k];
        g_wu[w] = s;
    }
    if (w == 0) g_B[d] = g_p3[3 * BLOCK_P + d];
}

// ---------------- main batch kernel --------------------------------------------
// CTA = 128 threads = 4 warps; warp = 32 rows (two m16 tiles); grid = 4096.
__global__ __launch_bounds__(128, 4)
void cnf_mma_kernel(const float* __restrict__ z, float* __restrict__ out) {
    __shared__ __align__(16) uint8_t sWh[WIDTH * SROW];
    __shared__ __align__(16) uint8_t sUth[WIDTH * SROW];
    __shared__ float sB[WIDTH];
    __shared__ float swu[WIDTH];

    const int tid = threadIdx.x;

    // stage weights (128B global rows -> 144B pitch smem)
    {
        const uint4* s0 = (const uint4*)g_wh16;
        const uint4* s1 = (const uint4*)g_uth16;
#pragma unroll
        for (int i = tid; i < 512; i += 128) {
            int r = i >> 3, c = i & 7;
            int dst = r * SROW + c * 16;
            *(uint4*)(sWh + dst)  = s0[i];
            *(uint4*)(sUth + dst) = s1[i];
        }
        if (tid < WIDTH) { sB[tid] = g_B[tid]; swu[tid] = g_wu[tid]; }
    }
    __syncthreads();

    const int lane = tid & 31;
    const int warp = tid >> 5;
    const int g = lane >> 2;     // group (row within 8)
    const int t = lane & 3;      // thread in group
    const int rrow = lane & 7;   // ldmatrix row provider
    const int qq = lane >> 3;    // ldmatrix matrix id

    const uint32_t baseWh  = smem_u32(sWh);
    const uint32_t baseUth = smem_u32(sUth);
    const float inv = 1.0f / (float)WIDTH;

    const size_t rowbase = (size_t)blockIdx.x * 128 + (size_t)warp * 32;

    // ---- load z rows (2 m-tiles) as float4 -> fp16 A frags ---------------------
    uint32_t zh[2][4][4];
#pragma unroll
    for (int m = 0; m < 2; m++) {
        const size_t rm = rowbase + 16 * m + g;
        const float4* zr0 = (const float4*)(z + rm * D_);
        const float4* zr1 = (const float4*)(z + (rm + 8) * D_);
#pragma unroll
        for (int kt = 0; kt < 4; kt++) {
            float4 v0 = zr0[4 * kt + t];
            float4 v1 = zr1[4 * kt + t];
            zh[m][kt][0] = pack_h2(make_float2(v0.x, v0.y));
            zh[m][kt][1] = pack_h2(make_float2(v1.x, v1.y));
            zh[m][kt][2] = pack_h2(make_float2(v0.z, v0.w));
            zh[m][kt][3] = pack_h2(make_float2(v1.z, v1.w));
        }
    }

    // ---- GEMM1: S = zh * Wh (both m-tiles share each ldsm) ----------------------
    float S[2][8][4];
#pragma unroll
    for (int n = 0; n < 8; n++) {
        const uint32_t off = (uint32_t)((8 * n + rrow) * SROW + qq * 16);
        uint32_t bh[8];
        ldsm_x4(&bh[0], baseWh + off);
        ldsm_x4(&bh[4], baseWh + off + 64);
#pragma unroll
        for (int i = 0; i < 4; i++) { S[0][n][i] = 0.0f; S[1][n][i] = 0.0f; }
#pragma unroll
        for (int kt = 0; kt < 4; kt++) {
            mma_f16(S[0][n], zh[0][kt], &bh[2 * kt], S[0][n]);
            mma_f16(S[1][n], zh[1][kt], &bh[2 * kt], S[1][n]);
        }
    }

    // ---- epilogue: h = tanh(S+B), trace, fp16 A2 frags ---------------------------
    uint32_t hh[2][4][4];
    float tr[2][2] = {{0.0f, 0.0f}, {0.0f, 0.0f}};
#pragma unroll
    for (int m = 0; m < 2; m++) {
#pragma unroll
        for (int n = 0; n < 8; n++) {
            float2 bb = *(const float2*)&sB[8 * n + 2 * t];
            float2 ww = *(const float2*)&swu[8 * n + 2 * t];
            float h0 = fast_tanh(S[m][n][0] + bb.x);
            float h1 = fast_tanh(S[m][n][1] + bb.y);
            float h2 = fast_tanh(S[m][n][2] + bb.x);
            float h3 = fast_tanh(S[m][n][3] + bb.y);
            tr[m][0] = fmaf(1.0f - h0 * h0, ww.x, tr[m][0]);
            tr[m][0] = fmaf(1.0f - h1 * h1, ww.y, tr[m][0]);
            tr[m][1] = fmaf(1.0f - h2 * h2, ww.x, tr[m][1]);
            tr[m][1] = fmaf(1.0f - h3 * h3, ww.y, tr[m][1]);
            int kt = n >> 1;
            int o = (n & 1) ? 2 : 0;
            hh[m][kt][o]     = pack_h2(make_float2(h0, h1));
            hh[m][kt][o + 1] = pack_h2(make_float2(h2, h3));
        }
    }

    // ---- GEMM2: DZ = hh * Uth ------------------------------------------------------
    float DZ[2][8][4];
#pragma unroll
    for (int n = 0; n < 8; n++) {
        const uint32_t off = (uint32_t)((8 * n + rrow) * SROW + qq * 16);
        uint32_t bh[8];
        ldsm_x4(&bh[0], baseUth + off);
        ldsm_x4(&bh[4], baseUth + off + 64);
#pragma unroll
        for (int i = 0; i < 4; i++) { DZ[0][n][i] = 0.0f; DZ[1][n][i] = 0.0f; }
#pragma unroll
        for (int kt = 0; kt < 4; kt++) {
            mma_f16(DZ[0][n], hh[0][kt], &bh[2 * kt], DZ[0][n]);
            mma_f16(DZ[1][n], hh[1][kt], &bh[2 * kt], DZ[1][n]);
        }
    }

    // ---- store dz/64 as float4 -------------------------------------------------------
#pragma unroll
    for (int m = 0; m < 2; m++) {
        const size_t rm = rowbase + 16 * m + g;
#pragma unroll
        for (int j = 0; j < 4; j++) {
            int col = 16 * j + 4 * t;
            *(float4*)(out + rm * D_ + col) =
                make_float4(DZ[m][2 * j][0] * inv, DZ[m][2 * j][1] * inv,
                            DZ[m][2 * j + 1][0] * inv, DZ[m][2 * j + 1][1] * inv);
            *(float4*)(out + (rm + 8) * D_ + col) =
                make_float4(DZ[m][2 * j][2] * inv, DZ[m][2 * j][3] * inv,
                            DZ[m][2 * j + 1][2] * inv, DZ[m][2 * j + 1][3] * inv);
        }
    }

    // ---- trace: reduce over quad, write -tr/64 ----------------------------------------
#pragma unroll
    for (int m = 0; m < 2; m++)
#pragma unroll
        for (int rh = 0; rh < 2; rh++) {
            float v = tr[m][rh];
            v += __shfl_xor_sync(0xFFFFFFFFu, v, 1);
            v += __shfl_xor_sync(0xFFFFFFFFu, v, 2);
            tr[m][rh] = v;
        }
    {
        float trv = (t == 0) ? tr[0][0] : (t == 1) ? tr[0][1]
                  : (t == 2) ? tr[1][0] : tr[1][1];
        size_t row = rowbase + (size_t)g + 8 * (t & 1) + 16 * (t >> 1);
        out[(size_t)BATCH * D_ + row] = -trv * inv;
    }
}

// ---------------------------------------------------------------------------
extern "C" void kernel_launch(void* const* d_in, const int* in_sizes, int n_in,
                              void* d_out, int out_size) {
    const float* t  = (const float*)d_in[0];
    const float* z  = (const float*)d_in[1];
    const float* W1 = (const float*)d_in[3];
    const float* b1 = (const float*)d_in[4];
    const float* W2 = (const float*)d_in[5];
    const float* b2 = (const float*)d_in[6];
    const float* W3 = (const float*)d_in[7];
    const float* b3 = (const float*)d_in[8];
    float* out = (float*)d_out;

    hyperA_kernel<<<64, 256>>>(t, W1, b1, W2, b2);
    hyperB_kernel<<<(NP + 31) / 32, 512>>>(W3, b3);
    hyper3_kernel<<<WIDTH, D_>>>();
    cnf_mma_kernel<<<BATCH / 128, 128>>>(z, out);
}

// round 12
// speedup vs baseline: 1.9939x; 1.0596x over previous
#include <cuda_runtime.h>
#include <cuda_fp16.h>
#include <cstdint>

// ---------------------------------------------------------------------------
// CNF_59133109731627 — round 12: R11 + epilogue fusion.
//  tanh fused into GEMM1 n-loop (S never materialized), dz stores fused into
//  GEMM2 n-pair loop (DZ live = 16 floats). Peak regs ~96 -> 5 CTAs/SM.
// ---------------------------------------------------------------------------

#define D_      64
#define HID     512
#define WIDTH   64
#define BATCH   524288
#define BLOCK_P (WIDTH * D_)            // 4096
#define NP      (3 * BLOCK_P + WIDTH)   // 12352
#define SROW    144                     // padded smem row pitch (bytes)

// ---------------- device scratch ---------------------------------------------
__device__ float g_p2[HID];
__device__ float g_p3[NP];
__device__ __align__(16) __half g_wh16[BLOCK_P];    // W  [w][dp] fp16 (d-cols permuted)
__device__ __align__(16) __half g_uth16[BLOCK_P];   // U^T[dp][w] fp16 (d-rows permuted)
__device__ float g_B[WIDTH];
__device__ float g_wu[WIDTH];

// ---------------- helpers -----------------------------------------------------
__device__ __forceinline__ float fast_tanh(float x) {
    float e = __expf(2.0f * x);
    return 1.0f - __fdividef(2.0f, e + 1.0f);
}

__device__ __forceinline__ uint32_t smem_u32(const void* p) {
    uint32_t a;
    asm("{ .reg .u64 t; cvta.to.shared.u64 t, %1; cvt.u32.u64 %0, t; }"
        : "=r"(a) : "l"(p));
    return a;
}

__device__ __forceinline__ void mma_f16(float d[4], const uint32_t a[4],
                                        const uint32_t b[2], const float c[4]) {
    asm volatile(
        "mma.sync.aligned.m16n8k16.row.col.f32.f16.f16.f32 "
        "{%0,%1,%2,%3}, {%4,%5,%6,%7}, {%8,%9}, {%10,%11,%12,%13};\n"
        : "=f"(d[0]), "=f"(d[1]), "=f"(d[2]), "=f"(d[3])
        : "r"(a[0]), "r"(a[1]), "r"(a[2]), "r"(a[3]),
          "r"(b[0]), "r"(b[1]),
          "f"(c[0]), "f"(c[1]), "f"(c[2]), "f"(c[3]));
}

__device__ __forceinline__ void ldsm_x4(uint32_t r[4], uint32_t saddr) {
    asm volatile(
        "ldmatrix.sync.aligned.m8n8.x4.shared.b16 {%0,%1,%2,%3}, [%4];"
        : "=r"(r[0]), "=r"(r[1]), "=r"(r[2]), "=r"(r[3]) : "r"(saddr));
}

__device__ __forceinline__ uint32_t pack_h2(float2 v) {
    __half2 h = __float22half2_rn(v);
    return *(uint32_t*)&h;
}

// ---------------- hyperA: p2 = tanh(tanh(t*W1+b1) @ W2 + b2) -------------------
__global__ void hyperA_kernel(const float* __restrict__ t,
                              const float* __restrict__ W1,
                              const float* __restrict__ b1,
                              const float* __restrict__ W2,
                              const float* __restrict__ b2) {
    __shared__ float p1[HID];
    __shared__ float red[32][8];
    const int tid = threadIdx.x;
    float tv = t[0];
    for (int k = tid; k < HID; k += 256)
        p1[k] = tanhf(tv * W1[k] + b1[k]);
    __syncthreads();
    const int x = tid & 7, y = tid >> 3;
    const int j = blockIdx.x * 8 + x;
    float acc = 0.0f;
#pragma unroll
    for (int i = 0; i < 16; i++) {
        int k = y + 32 * i;
        acc = fmaf(p1[k], W2[(size_t)k * HID + j], acc);
    }
    red[y][x] = acc;
    __syncthreads();
    if (tid < 8) {
        float s = b2[blockIdx.x * 8 + tid];
#pragma unroll
        for (int yy = 0; yy < 32; yy++) s += red[yy][tid];
        g_p2[blockIdx.x * 8 + tid] = tanhf(s);
    }
}

// ---------------- hyperB: p3 = p2 @ W3 + b3 ------------------------------------
__global__ void hyperB_kernel(const float* __restrict__ W3,
                              const float* __restrict__ b3) {
    __shared__ float s2[HID];
    __shared__ float red[16][33];
    const int tid = threadIdx.x;
    if (tid < HID) s2[tid] = g_p2[tid];
    __syncthreads();
    const int x = tid & 31, y = tid >> 5;
    const int j = blockIdx.x * 32 + x;
    const bool ok = j < NP;
    float acc = 0.0f;
    if (ok) {
#pragma unroll
        for (int i = 0; i < 32; i++) {
            int k = y + 16 * i;
            acc = fmaf(s2[k], W3[(size_t)k * NP + j], acc);
        }
    }
    red[y][x] = acc;
    __syncthreads();
    if (y == 0 && ok) {
        float s = b3[j];
#pragma unroll
        for (int yy = 0; yy < 16; yy++) s += red[yy][x];
        g_p3[j] = s;
    }
}

// ---------------- hyper3: param prep (fp16, d-permuted) -------------------------
__global__ void hyper3_kernel() {
    __shared__ float prod[WIDTH];
    int w = blockIdx.x, d = threadIdx.x;
    int idx = w * D_ + d;
    float Wv = g_p3[idx];
    float gv = g_p3[2 * BLOCK_P + idx];
    float Uv = g_p3[BLOCK_P + idx] * (1.0f / (1.0f + __expf(-gv)));

    int dd = d & 15;
    int f = ((dd >> 1) & 1) * 8 + (dd >> 2) * 2 + (dd & 1);
    int dp = (d & ~15) | f;

    g_wh16[w * D_ + dp] = __float2half_rn(Wv);
    g_uth16[dp * WIDTH + w] = __float2half_rn(Uv);

    prod[d] = Wv * Uv;
    __syncthreads();
    if (d == 0) {
        float s = 0.0f;
#pragma unroll
        for (int k = 0; k < D_; k++) s += prod[k];
        g_wu[w] = s;
    }
    if (w == 0) g_B[d] = g_p3[3 * BLOCK_P + d];
}

// ---------------- main batch kernel --------------------------------------------
// CTA = 128 threads = 4 warps; warp = 32 rows (two m16 tiles); grid = 4096.
__global__ __launch_bounds__(128, 5)
void cnf_mma_kernel(const float* __restrict__ z, float* __restrict__ out) {
    __shared__ __align__(16) uint8_t sWh[WIDTH * SROW];
    __shared__ __align__(16) uint8_t sUth[WIDTH * SROW];
    __shared__ float sB[WIDTH];
    __shared__ float swu[WIDTH];

    const int tid = threadIdx.x;

    // stage weights (128B global rows -> 144B pitch smem)
    {
        const uint4* s0 = (const uint4*)g_wh16;
        const uint4* s1 = (const uint4*)g_uth16;
#pragma unroll
        for (int i = tid; i < 512; i += 128) {
            int r = i >> 3, c = i & 7;
            int dst = r * SROW + c * 16;
            *(uint4*)(sWh + dst)  = s0[i];
            *(uint4*)(sUth + dst) = s1[i];
        }
        if (tid < WIDTH) { sB[tid] = g_B[tid]; swu[tid] = g_wu[tid]; }
    }
    __syncthreads();

    const int lane = tid & 31;
    const int warp = tid >> 5;
    const int g = lane >> 2;     // group (row within 8)
    const int t = lane & 3;      // thread in group
    const int rrow = lane & 7;   // ldmatrix row provider
    const int qq = lane >> 3;    // ldmatrix matrix id

    const uint32_t baseWh  = smem_u32(sWh);
    const uint32_t baseUth = smem_u32(sUth);
    const float inv = 1.0f / (float)WIDTH;

    const size_t rowbase = (size_t)blockIdx.x * 128 + (size_t)warp * 32;

    // ---- load z rows (2 m-tiles) as float4 -> fp16 A frags ---------------------
    uint32_t zh[2][4][4];
#pragma unroll
    for (int m = 0; m < 2; m++) {
        const size_t rm = rowbase + 16 * m + g;
        const float4* zr0 = (const float4*)(z + rm * D_);
        const float4* zr1 = (const float4*)(z + (rm + 8) * D_);
#pragma unroll
        for (int kt = 0; kt < 4; kt++) {
            float4 v0 = zr0[4 * kt + t];
            float4 v1 = zr1[4 * kt + t];
            zh[m][kt][0] = pack_h2(make_float2(v0.x, v0.y));
            zh[m][kt][1] = pack_h2(make_float2(v1.x, v1.y));
            zh[m][kt][2] = pack_h2(make_float2(v0.z, v0.w));
            zh[m][kt][3] = pack_h2(make_float2(v1.z, v1.w));
        }
    }

    // ---- GEMM1 + fused epilogue: per n-tile compute S, tanh, pack --------------
    uint32_t hh[2][4][4];
    float tr[2][2] = {{0.0f, 0.0f}, {0.0f, 0.0f}};
#pragma unroll
    for (int n = 0; n < 8; n++) {
        const uint32_t off = (uint32_t)((8 * n + rrow) * SROW + qq * 16);
        uint32_t bh[8];
        ldsm_x4(&bh[0], baseWh + off);
        ldsm_x4(&bh[4], baseWh + off + 64);
        float S0[4] = {0.0f, 0.0f, 0.0f, 0.0f};
        float S1[4] = {0.0f, 0.0f, 0.0f, 0.0f};
#pragma unroll
        for (int kt = 0; kt < 4; kt++) {
            mma_f16(S0, zh[0][kt], &bh[2 * kt], S0);
            mma_f16(S1, zh[1][kt], &bh[2 * kt], S1);
        }
        const float2 bb = *(const float2*)&sB[8 * n + 2 * t];
        const float2 ww = *(const float2*)&swu[8 * n + 2 * t];
        const int kt = n >> 1;
        const int o = (n & 1) ? 2 : 0;
        {
            float h0 = fast_tanh(S0[0] + bb.x);
            float h1 = fast_tanh(S0[1] + bb.y);
            float h2 = fast_tanh(S0[2] + bb.x);
            float h3 = fast_tanh(S0[3] + bb.y);
            tr[0][0] = fmaf(1.0f - h0 * h0, ww.x, tr[0][0]);
            tr[0][0] = fmaf(1.0f - h1 * h1, ww.y, tr[0][0]);
            tr[0][1] = fmaf(1.0f - h2 * h2, ww.x, tr[0][1]);
            tr[0][1] = fmaf(1.0f - h3 * h3, ww.y, tr[0][1]);
            hh[0][kt][o]     = pack_h2(make_float2(h0, h1));
            hh[0][kt][o + 1] = pack_h2(make_float2(h2, h3));
        }
        {
            float h0 = fast_tanh(S1[0] + bb.x);
            float h1 = fast_tanh(S1[1] + bb.y);
            float h2 = fast_tanh(S1[2] + bb.x);
            float h3 = fast_tanh(S1[3] + bb.y);
            tr[1][0] = fmaf(1.0f - h0 * h0, ww.x, tr[1][0]);
            tr[1][0] = fmaf(1.0f - h1 * h1, ww.y, tr[1][0]);
            tr[1][1] = fmaf(1.0f - h2 * h2, ww.x, tr[1][1]);
            tr[1][1] = fmaf(1.0f - h3 * h3, ww.y, tr[1][1]);
            hh[1][kt][o]     = pack_h2(make_float2(h0, h1));
            hh[1][kt][o + 1] = pack_h2(make_float2(h2, h3));
        }
    }

    // ---- GEMM2 + fused stores: per n-pair compute DZ and store float4 ----------
#pragma unroll
    for (int j = 0; j < 4; j++) {
        float DZ[2][2][4];
#pragma unroll
        for (int p = 0; p < 2; p++) {
            const int n = 2 * j + p;
            const uint32_t off = (uint32_t)((8 * n + rrow) * SROW + qq * 16);
            uint32_t bh[8];
            ldsm_x4(&bh[0], baseUth + off);
            ldsm_x4(&bh[4], baseUth + off + 64);
#pragma unroll
            for (int i = 0; i < 4; i++) { DZ[0][p][i] = 0.0f; DZ[1][p][i] = 0.0f; }
#pragma unroll
            for (int kt = 0; kt < 4; kt++) {
                mma_f16(DZ[0][p], hh[0][kt], &bh[2 * kt], DZ[0][p]);
                mma_f16(DZ[1][p], hh[1][kt], &bh[2 * kt], DZ[1][p]);
            }
        }
        const int col = 16 * j + 4 * t;
#pragma unroll
        for (int m = 0; m < 2; m++) {
            const size_t rm = rowbase + 16 * m + g;
            *(float4*)(out + rm * D_ + col) =
                make_float4(DZ[m][0][0] * inv, DZ[m][0][1] * inv,
                            DZ[m][1][0] * inv, DZ[m][1][1] * inv);
            *(float4*)(out + (rm + 8) * D_ + col) =
                make_float4(DZ[m][0][2] * inv, DZ[m][0][3] * inv,
                            DZ[m][1][2] * inv, DZ[m][1][3] * inv);
        }
    }

    // ---- trace: reduce over quad, write -tr/64 ----------------------------------
#pragma unroll
    for (int m = 0; m < 2; m++)
#pragma unroll
        for (int rh = 0; rh < 2; rh++) {
            float v = tr[m][rh];
            v += __shfl_xor_sync(0xFFFFFFFFu, v, 1);
            v += __shfl_xor_sync(0xFFFFFFFFu, v, 2);
            tr[m][rh] = v;
        }
    {
        float trv = (t == 0) ? tr[0][0] : (t == 1) ? tr[0][1]
                  : (t == 2) ? tr[1][0] : tr[1][1];
        size_t row = rowbase + (size_t)g + 8 * (t & 1) + 16 * (t >> 1);
        out[(size_t)BATCH * D_ + row] = -trv * inv;
    }
}

// ---------------------------------------------------------------------------
extern "C" void kernel_launch(void* const* d_in, const int* in_sizes, int n_in,
                              void* d_out, int out_size) {
    const float* t  = (const float*)d_in[0];
    const float* z  = (const float*)d_in[1];
    const float* W1 = (const float*)d_in[3];
    const float* b1 = (const float*)d_in[4];
    const float* W2 = (const float*)d_in[5];
    const float* b2 = (const float*)d_in[6];
    const float* W3 = (const float*)d_in[7];
    const float* b3 = (const float*)d_in[8];
    float* out = (float*)d_out;

    hyperA_kernel<<<64, 256>>>(t, W1, b1, W2, b2);
    hyperB_kernel<<<(NP + 31) / 32, 512>>>(W3, b3);
    hyper3_kernel<<<WIDTH, D_>>>();
    cnf_mma_kernel<<<BATCH / 128, 128>>>(z, out);
}